// round 1
// baseline (speedup 1.0000x reference)
#include <cuda_runtime.h>
#include <math.h>

#define D_ 128
#define NMAX 50016
#define EPMAX 550032
#define MAXN 0.99999f
#define MINNORM 1e-15f

// ---------------- scratch (static __device__, allowed) ----------------
__device__ float g_xe[NMAX * D_];
__device__ float g_xh[NMAX * D_];
__device__ float g_lx[NMAX * D_];
__device__ float g_agg_e[NMAX * D_];
__device__ float g_agg_h[NMAX * D_];
__device__ float g_ai[NMAX * 4];
__device__ float g_aj[NMAX * 4];
__device__ float g_hi[NMAX * 4];
__device__ float g_hj[NMAX * 4];
__device__ float g_x2[NMAX];
__device__ float g_sum_d[NMAX];
__device__ float g_sum_e[NMAX * 4];
__device__ float g_sum_h[NMAX * 4];
__device__ float g_de[EPMAX];
__device__ float g_le[EPMAX * 4];
__device__ float g_ah[EPMAX * 4];
__device__ float g_WtE[D_ * D_];
__device__ float g_WtH[D_ * D_];

// ---------------- helpers ----------------
__device__ __forceinline__ float atanhc(float x) {
    x = fminf(fmaxf(x, -1.0f + 1e-7f), 1.0f - 1e-7f);
    return atanhf(x);
}
__device__ __forceinline__ float wsum(float v) {
#pragma unroll
    for (int o = 16; o; o >>= 1) v += __shfl_xor_sync(0xffffffffu, v, o);
    return v;
}
__device__ __forceinline__ float d4(float4 a, float4 b) {
    return a.x * b.x + a.y * b.y + a.z * b.z + a.w * b.w;
}
__device__ __forceinline__ float4 f4s(float4 a, float s) {
    return make_float4(a.x * s, a.y * s, a.z * s, a.w * s);
}
__device__ __forceinline__ float4 f4axby(float a, float4 x, float b, float4 y) {
    return make_float4(a * x.x + b * y.x, a * x.y + b * y.y,
                       a * x.z + b * y.z, a * x.w + b * y.w);
}
// project onto Poincare ball; warp-collective (recomputes norm like the reference)
__device__ __forceinline__ void projw(float4 &v) {
    float n = fmaxf(sqrtf(wsum(d4(v, v))), MINNORM);
    if (n > MAXN) {
        float s = MAXN / n;
        v.x *= s; v.y *= s; v.z *= s; v.w *= s;
    }
}
__device__ __forceinline__ float lrelu(float v) { return v >= 0.f ? v : 0.2f * v; }

// ---------------- kernels ----------------
__global__ __launch_bounds__(256) void zero_kernel(int N) {
    int i = blockIdx.x * blockDim.x + threadIdx.x;
    if (i < N * D_) { g_agg_e[i] = 0.f; g_agg_h[i] = 0.f; }
    if (i < N) g_sum_d[i] = 0.f;
    if (i < 4 * N) { g_sum_e[i] = 0.f; g_sum_h[i] = 0.f; }
}

__global__ __launch_bounds__(256) void transpose_kernel(const float* __restrict__ We,
                                                        const float* __restrict__ Wh) {
    int i = blockIdx.x * blockDim.x + threadIdx.x;
    if (i >= 2 * D_ * D_) return;
    int m = i >> 14;
    int k = (i >> 7) & 127;
    int c = i & 127;
    if (m == 0) g_WtE[k * D_ + c] = We[c * D_ + k];
    else        g_WtH[k * D_ + c] = Wh[c * D_ + k];
}

// Euclidean branch per-node: xe = x_e @ W_e^T + b ; a_i/a_j head dots.
// warp per node, lane l owns channels 4l..4l+3
__global__ __launch_bounds__(128) void node_e_kernel(const float* __restrict__ x,
                                                     const float* __restrict__ b_lin,
                                                     const float* __restrict__ att,
                                                     int N) {
    __shared__ float sx[4][D_];
    int w = threadIdx.x >> 5, l = threadIdx.x & 31;
    int n = blockIdx.x * 4 + w;
    if (n >= N) return;
    float4 xv = ((const float4*)x)[n * 32 + l];
    ((float4*)sx[w])[l] = xv;
    __syncwarp();
    float4 acc = make_float4(0.f, 0.f, 0.f, 0.f);
    const float4* Wt = (const float4*)g_WtE;
#pragma unroll 8
    for (int k = 0; k < D_; k++) {
        float s = sx[w][k];
        float4 wv = Wt[k * 32 + l];
        acc.x = fmaf(s, wv.x, acc.x);
        acc.y = fmaf(s, wv.y, acc.y);
        acc.z = fmaf(s, wv.z, acc.z);
        acc.w = fmaf(s, wv.w, acc.w);
    }
    float4 bv = ((const float4*)b_lin)[l];
    acc.x += bv.x; acc.y += bv.y; acc.z += bv.z; acc.w += bv.w;
    ((float4*)g_xe)[n * 32 + l] = acc;
    int h = l >> 3, j0 = (l & 7) * 4;
    const float* at = att + h * 64 + j0;
    float pi = acc.x * at[0] + acc.y * at[1] + acc.z * at[2] + acc.w * at[3];
    const float* at2 = at + 32;
    float pj = acc.x * at2[0] + acc.y * at2[1] + acc.z * at2[2] + acc.w * at2[3];
#pragma unroll
    for (int o = 4; o; o >>= 1) {
        pi += __shfl_down_sync(0xffffffffu, pi, o, 8);
        pj += __shfl_down_sync(0xffffffffu, pj, o, 8);
    }
    if ((l & 7) == 0) { g_ai[n * 4 + h] = pi; g_aj[n * 4 + h] = pj; }
}

// Hyperbolic branch per-node: mobius_matvec + proj + mobius_add(bias) + proj,
// store xh, ||xh||^2, lx = logmap0(xh), head dots hi/hj.
__global__ __launch_bounds__(128) void node_h_kernel(const float* __restrict__ x,
                                                     const float* __restrict__ b_lin,
                                                     const float* __restrict__ att,
                                                     int N) {
    __shared__ float sx[4][D_];
    int w = threadIdx.x >> 5, l = threadIdx.x & 31;
    int n = blockIdx.x * 4 + w;
    if (n >= N) return;
    float4 xv = ((const float4*)x)[n * 32 + l];
    ((float4*)sx[w])[l] = xv;
    __syncwarp();
    float n_x = fmaxf(sqrtf(wsum(d4(xv, xv))), MINNORM);
    float4 acc = make_float4(0.f, 0.f, 0.f, 0.f);
    const float4* Wt = (const float4*)g_WtH;
#pragma unroll 8
    for (int k = 0; k < D_; k++) {
        float s = sx[w][k];
        float4 wv = Wt[k * 32 + l];
        acc.x = fmaf(s, wv.x, acc.x);
        acc.y = fmaf(s, wv.y, acc.y);
        acc.z = fmaf(s, wv.z, acc.z);
        acc.w = fmaf(s, wv.w, acc.w);
    }
    float n_mx = fmaxf(sqrtf(wsum(d4(acc, acc))), MINNORM);
    float f = tanhf(n_mx / n_x * atanhc(n_x)) / n_mx;
    float4 mv = f4s(acc, f);
    projw(mv);
    // hb = proj(expmap0(b_lin_h))
    float4 bv = ((const float4*)b_lin)[l];
    float nb = fmaxf(sqrtf(wsum(d4(bv, bv))), MINNORM);
    float4 hb = f4s(bv, tanhf(nb) / nb);
    projw(hb);
    // xh = proj(mobius_add(mv, hb))
    float x2 = wsum(d4(mv, mv));
    float y2 = wsum(d4(hb, hb));
    float xy = wsum(d4(mv, hb));
    float A = 1.f + 2.f * xy + y2, B = 1.f - x2;
    float den = fmaxf(1.f + 2.f * xy + x2 * y2, MINNORM);
    float4 xh = f4s(f4axby(A, mv, B, hb), 1.f / den);
    projw(xh);
    ((float4*)g_xh)[n * 32 + l] = xh;
    float x2f = wsum(d4(xh, xh));
    if (l == 0) g_x2[n] = x2f;
    float nxh = fmaxf(sqrtf(x2f), MINNORM);
    float4 lx = f4s(xh, atanhc(nxh) / nxh);
    ((float4*)g_lx)[n * 32 + l] = lx;
    int h = l >> 3, j0 = (l & 7) * 4;
    const float* at = att + h * 64 + j0;
    float pi = lx.x * at[0] + lx.y * at[1] + lx.z * at[2] + lx.w * at[3];
    const float* at2 = at + 32;
    float pj = lx.x * at2[0] + lx.y * at2[1] + lx.z * at2[2] + lx.w * at2[3];
#pragma unroll
    for (int o = 4; o; o >>= 1) {
        pi += __shfl_down_sync(0xffffffffu, pi, o, 8);
        pj += __shfl_down_sync(0xffffffffu, pj, o, 8);
    }
    if ((l & 7) == 0) { g_hi[n * 4 + h] = pi; g_hj[n * 4 + h] = pj; }
}

// Edge pass 1 (warp/edge): hyperbolic edge distance + euclid logits + exp-sums
__global__ __launch_bounds__(256) void edge1_kernel(const int* __restrict__ ei, int E, int EP) {
    int w = (blockIdx.x * blockDim.x + threadIdx.x) >> 5;
    int l = threadIdx.x & 31;
    if (w >= EP) return;
    int s, dn;
    if (w < E) { s = ei[w]; dn = ei[E + w]; } else { s = dn = w - E; }
    float4 xd = ((const float4*)g_xh)[dn * 32 + l];
    float4 xs = ((const float4*)g_xh)[s * 32 + l];
    float xy = wsum(d4(xd, xs));
    float x2 = g_x2[dn], y2 = g_x2[s];
    float A = 1.f - 2.f * xy + y2, B = 1.f - x2;
    float den = fmaxf(1.f - 2.f * xy + x2 * y2, MINNORM);
    float num2 = fmaxf(A * A * x2 + B * B * y2 - 2.f * A * B * xy, 0.f);
    float dd = 2.f * atanhc(sqrtf(num2) / den);
    if (l == 0) {
        g_de[w] = dd;
        atomicAdd(&g_sum_d[dn], expf(dd));
    }
    if (l < 4) {
        float le = lrelu(g_ai[dn * 4 + l] + g_aj[s * 4 + l]);
        g_le[w * 4 + l] = le;
        atomicAdd(&g_sum_e[dn * 4 + l], expf(le));
    }
}

// Edge pass 2 (thread/edge): distance softmax -> hyperbolic logits + exp-sums
__global__ __launch_bounds__(256) void edge2_kernel(const int* __restrict__ ei, int E, int EP) {
    int e = blockIdx.x * blockDim.x + threadIdx.x;
    if (e >= EP) return;
    int s, dn;
    if (e < E) { s = ei[e]; dn = ei[E + e]; } else { s = dn = e - E; }
    float dsm = expf(g_de[e]) / (g_sum_d[dn] + 1e-16f);
    float4 hi = ((const float4*)g_hi)[dn];
    float4 hj = ((const float4*)g_hj)[s];
    float4 a;
    a.x = lrelu((hi.x + hj.x) * dsm);
    a.y = lrelu((hi.y + hj.y) * dsm);
    a.z = lrelu((hi.z + hj.z) * dsm);
    a.w = lrelu((hi.w + hj.w) * dsm);
    ((float4*)g_ah)[e] = a;
    atomicAdd(&g_sum_h[dn * 4 + 0], expf(a.x));
    atomicAdd(&g_sum_h[dn * 4 + 1], expf(a.y));
    atomicAdd(&g_sum_h[dn * 4 + 2], expf(a.z));
    atomicAdd(&g_sum_h[dn * 4 + 3], expf(a.w));
}

// Edge pass 3 (warp/edge): weighted scatter-add into agg_e / agg_h
__global__ __launch_bounds__(256) void edge3_kernel(const int* __restrict__ ei, int E, int EP) {
    int w = (blockIdx.x * blockDim.x + threadIdx.x) >> 5;
    int l = threadIdx.x & 31;
    if (w >= EP) return;
    int s, dn;
    if (w < E) { s = ei[w]; dn = ei[E + w]; } else { s = dn = w - E; }
    int h = l >> 3;
    float we = expf(g_le[w * 4 + h]) / (g_sum_e[dn * 4 + h] + 1e-16f);
    float wh = expf(g_ah[w * 4 + h]) / (g_sum_h[dn * 4 + h] + 1e-16f);
    float4 xs = ((const float4*)g_xe)[s * 32 + l];
    float4 ls = ((const float4*)g_lx)[s * 32 + l];
    float* pe = g_agg_e + dn * D_ + 4 * l;
    float* ph = g_agg_h + dn * D_ + 4 * l;
    atomicAdd(pe + 0, xs.x * we);
    atomicAdd(pe + 1, xs.y * we);
    atomicAdd(pe + 2, xs.z * we);
    atomicAdd(pe + 3, xs.w * we);
    atomicAdd(ph + 0, ls.x * wh);
    atomicAdd(ph + 1, ls.y * wh);
    atomicAdd(ph + 2, ls.z * wh);
    atomicAdd(ph + 3, ls.w * wh);
}

// Finalize per-node: e_out/h_out, HFusion, EFusion, write [2,N,D]
__global__ __launch_bounds__(128) void finalize_kernel(const float* __restrict__ b_e,
                                                       const float* __restrict__ b_h,
                                                       const float* __restrict__ att_hf,
                                                       const float* __restrict__ att_ef,
                                                       float* __restrict__ out, int N) {
    int w = threadIdx.x >> 5, l = threadIdx.x & 31;
    int n = blockIdx.x * 4 + w;
    if (n >= N) return;
    float4 ae = ((const float4*)g_agg_e)[n * 32 + l];
    float4 be = ((const float4*)b_e)[l];
    float4 eo = make_float4(fmaxf(ae.x + be.x, 0.f), fmaxf(ae.y + be.y, 0.f),
                            fmaxf(ae.z + be.z, 0.f), fmaxf(ae.w + be.w, 0.f));
    float4 ag = ((const float4*)g_agg_h)[n * 32 + l];
    float4 bh = ((const float4*)b_h)[l];
    float4 ot = make_float4(fmaxf(ag.x + bh.x, 0.f), fmaxf(ag.y + bh.y, 0.f),
                            fmaxf(ag.z + bh.z, 0.f), fmaxf(ag.w + bh.w, 0.f));
    // h_out = proj(expmap0(out_t))
    float nt = fmaxf(sqrtf(wsum(d4(ot, ot))), MINNORM);
    float4 ho = f4s(ot, tanhf(nt) / nt);
    projw(ho);
    // ye = proj(expmap0(e_out))
    float ne = fmaxf(sqrtf(wsum(d4(eo, eo))), MINNORM);
    float4 ye = f4s(eo, tanhf(ne) / ne);
    projw(ye);
    // dist_f = pdist(h_out, ye) * att_hf
    float x2 = wsum(d4(ho, ho));
    float y2 = wsum(d4(ye, ye));
    float xy = wsum(d4(ho, ye));
    float A = 1.f - 2.f * xy + y2, B = 1.f - x2;
    float den = fmaxf(1.f - 2.f * xy + x2 * y2, MINNORM);
    float num2 = fmaxf(A * A * x2 + B * B * y2 - 2.f * A * B * xy, 0.f);
    float r = 2.f * atanhc(sqrtf(num2) / den) * att_hf[0];
    // xe2 = proj(mobius_scalar_mul(r, ye))
    float ny = fmaxf(sqrtf(y2), MINNORM);
    float4 xe2 = f4s(ye, tanhf(r * atanhc(ny)) / ny);
    projw(xe2);
    // h_fused = proj(mobius_add(ho, xe2))
    float y2b = wsum(d4(xe2, xe2));
    float xyb = wsum(d4(ho, xe2));
    float A2 = 1.f + 2.f * xyb + y2b, B2 = 1.f - x2;
    float den2 = fmaxf(1.f + 2.f * xyb + x2 * y2b, MINNORM);
    float4 hf = f4s(f4axby(A2, ho, B2, xe2), 1.f / den2);
    projw(hf);
    // e_fused = e_out + de * lh,  lh = logmap0(h_out)
    float nho = fmaxf(sqrtf(x2), MINNORM);
    float4 lh = f4s(ho, atanhc(nho) / nho);
    float4 df = make_float4(lh.x - eo.x, lh.y - eo.y, lh.z - eo.z, lh.w - eo.w);
    float de = wsum(d4(df, df)) * att_ef[0];
    float4 ef = make_float4(eo.x + de * lh.x, eo.y + de * lh.y,
                            eo.z + de * lh.z, eo.w + de * lh.w);
    ((float4*)out)[n * 32 + l] = hf;
    ((float4*)out)[(size_t)N * 32 + n * 32 + l] = ef;
}

// ---------------- launch ----------------
extern "C" void kernel_launch(void* const* d_in, const int* in_sizes, int n_in,
                              void* d_out, int out_size) {
    const float* x_e      = (const float*)d_in[0];
    const float* x_h      = (const float*)d_in[1];
    const int*   ei       = (const int*)d_in[2];
    const float* W_e      = (const float*)d_in[3];
    const float* b_lin_e  = (const float*)d_in[4];
    const float* att_e    = (const float*)d_in[5];
    const float* b_e      = (const float*)d_in[6];
    const float* W_h      = (const float*)d_in[7];
    const float* b_lin_h  = (const float*)d_in[8];
    const float* att_h    = (const float*)d_in[9];
    const float* b_h      = (const float*)d_in[10];
    const float* att_hf   = (const float*)d_in[11];
    const float* att_ef   = (const float*)d_in[12];
    float* out = (float*)d_out;

    int N  = in_sizes[0] / D_;
    int E  = in_sizes[2] / 2;
    int EP = E + N;

    zero_kernel<<<(N * D_ + 255) / 256, 256>>>(N);
    transpose_kernel<<<(2 * D_ * D_ + 255) / 256, 256>>>(W_e, W_h);
    node_e_kernel<<<(N + 3) / 4, 128>>>(x_e, b_lin_e, att_e, N);
    node_h_kernel<<<(N + 3) / 4, 128>>>(x_h, b_lin_h, att_h, N);
    edge1_kernel<<<(EP + 7) / 8, 256>>>(ei, E, EP);
    edge2_kernel<<<(EP + 255) / 256, 256>>>(ei, E, EP);
    edge3_kernel<<<(EP + 7) / 8, 256>>>(ei, E, EP);
    finalize_kernel<<<(N + 3) / 4, 128>>>(b_e, b_h, att_hf, att_ef, out, N);
}

// round 2
// speedup vs baseline: 1.8428x; 1.8428x over previous
#include <cuda_runtime.h>
#include <math.h>

#define D_ 128
#define NMAX 50016
#define EPMAX 550032
#define MAXN 0.99999f
#define MINNORM 1e-15f

// ---------------- scratch ----------------
__device__ float g_xe[NMAX * D_];
__device__ float g_xh[NMAX * D_];
__device__ float g_lx[NMAX * D_];
__device__ float g_ai[NMAX * 4];
__device__ float g_aj[NMAX * 4];
__device__ float g_hi[NMAX * 4];
__device__ float g_hj[NMAX * 4];
__device__ float g_x2[NMAX];
__device__ float g_de[EPMAX];
__device__ float g_le[EPMAX * 4];
__device__ float g_ah[EPMAX * 4];
__device__ float g_WtE[D_ * D_];
__device__ float g_WtH[D_ * D_];
__device__ int   g_deg[NMAX];
__device__ int   g_cur[NMAX];
__device__ int   g_start[NMAX + 1];
__device__ int   g_csrc[EPMAX];

// ---------------- helpers ----------------
__device__ __forceinline__ float atanhc(float x) {
    x = fminf(fmaxf(x, -1.0f + 1e-7f), 1.0f - 1e-7f);
    return atanhf(x);
}
__device__ __forceinline__ float wsum(float v) {
#pragma unroll
    for (int o = 16; o; o >>= 1) v += __shfl_xor_sync(0xffffffffu, v, o);
    return v;
}
__device__ __forceinline__ float d4(float4 a, float4 b) {
    return a.x * b.x + a.y * b.y + a.z * b.z + a.w * b.w;
}
__device__ __forceinline__ float4 f4s(float4 a, float s) {
    return make_float4(a.x * s, a.y * s, a.z * s, a.w * s);
}
__device__ __forceinline__ float4 f4axby(float a, float4 x, float b, float4 y) {
    return make_float4(a * x.x + b * y.x, a * x.y + b * y.y,
                       a * x.z + b * y.z, a * x.w + b * y.w);
}
__device__ __forceinline__ void projw(float4 &v) {
    float n = fmaxf(sqrtf(wsum(d4(v, v))), MINNORM);
    if (n > MAXN) {
        float s = MAXN / n;
        v.x *= s; v.y *= s; v.z *= s; v.w *= s;
    }
}
__device__ __forceinline__ float lrelu(float v) { return v >= 0.f ? v : 0.2f * v; }

// ---------------- CSR build ----------------
__global__ __launch_bounds__(256) void zero_kernel(int N) {
    int i = blockIdx.x * blockDim.x + threadIdx.x;
    if (i < N) { g_deg[i] = 0; g_cur[i] = 0; }
}

__global__ __launch_bounds__(256) void count_kernel(const int* __restrict__ ei, int E, int EP) {
    int e = blockIdx.x * blockDim.x + threadIdx.x;
    if (e >= EP) return;
    int dn = (e < E) ? ei[E + e] : (e - E);
    atomicAdd(&g_deg[dn], 1);
}

__global__ __launch_bounds__(1024) void scan_kernel(int N) {
    __shared__ int sums[1024];
    int t = threadIdx.x;
    int chunk = (N + 1023) >> 10;
    int b = t * chunk, e = min(b + chunk, N);
    int own = 0;
    for (int i = b; i < e; i++) own += g_deg[i];
    sums[t] = own;
    __syncthreads();
#pragma unroll
    for (int d = 1; d < 1024; d <<= 1) {
        int v = (t >= d) ? sums[t - d] : 0;
        __syncthreads();
        sums[t] += v;
        __syncthreads();
    }
    int off = sums[t] - own;
    for (int i = b; i < e; i++) { g_start[i] = off; off += g_deg[i]; }
    if (b < N && e == N) g_start[N] = off;
}

__global__ __launch_bounds__(256) void scatter_kernel(const int* __restrict__ ei, int E, int EP) {
    int e = blockIdx.x * blockDim.x + threadIdx.x;
    if (e >= EP) return;
    int s, dn;
    if (e < E) { s = ei[e]; dn = ei[E + e]; } else { s = dn = e - E; }
    int pos = atomicAdd(&g_cur[dn], 1);
    g_csrc[g_start[dn] + pos] = s;
}

__global__ __launch_bounds__(256) void transpose_kernel(const float* __restrict__ We,
                                                        const float* __restrict__ Wh) {
    int i = blockIdx.x * blockDim.x + threadIdx.x;
    if (i >= 2 * D_ * D_) return;
    int m = i >> 14;
    int k = (i >> 7) & 127;
    int c = i & 127;
    if (m == 0) g_WtE[k * D_ + c] = We[c * D_ + k];
    else        g_WtH[k * D_ + c] = Wh[c * D_ + k];
}

// ---------------- node kernels: 4 nodes per warp GEMM ----------------
__global__ __launch_bounds__(128) void node_e_kernel(const float* __restrict__ x,
                                                     const float* __restrict__ b_lin,
                                                     const float* __restrict__ att,
                                                     int N) {
    __shared__ float sx[4][4][D_];
    int w = threadIdx.x >> 5, l = threadIdx.x & 31;
    int base = blockIdx.x * 16 + w * 4;
    if (base >= N) return;
#pragma unroll
    for (int j = 0; j < 4; j++) {
        int n = min(base + j, N - 1);
        ((float4*)sx[w][j])[l] = ((const float4*)x)[n * 32 + l];
    }
    __syncwarp();
    float4 a0 = make_float4(0.f, 0.f, 0.f, 0.f), a1 = a0, a2 = a0, a3 = a0;
    const float4* Wt = (const float4*)g_WtE;
#pragma unroll 4
    for (int k = 0; k < D_; k++) {
        float4 wv = Wt[k * 32 + l];
        float s0 = sx[w][0][k], s1 = sx[w][1][k], s2 = sx[w][2][k], s3 = sx[w][3][k];
        a0.x = fmaf(s0, wv.x, a0.x); a0.y = fmaf(s0, wv.y, a0.y);
        a0.z = fmaf(s0, wv.z, a0.z); a0.w = fmaf(s0, wv.w, a0.w);
        a1.x = fmaf(s1, wv.x, a1.x); a1.y = fmaf(s1, wv.y, a1.y);
        a1.z = fmaf(s1, wv.z, a1.z); a1.w = fmaf(s1, wv.w, a1.w);
        a2.x = fmaf(s2, wv.x, a2.x); a2.y = fmaf(s2, wv.y, a2.y);
        a2.z = fmaf(s2, wv.z, a2.z); a2.w = fmaf(s2, wv.w, a2.w);
        a3.x = fmaf(s3, wv.x, a3.x); a3.y = fmaf(s3, wv.y, a3.y);
        a3.z = fmaf(s3, wv.z, a3.z); a3.w = fmaf(s3, wv.w, a3.w);
    }
    float4 bv = ((const float4*)b_lin)[l];
    float4 accs[4] = {a0, a1, a2, a3};
    int h = l >> 3, j0 = (l & 7) * 4;
    const float* at  = att + h * 64 + j0;
    const float* at2 = at + 32;
#pragma unroll
    for (int j = 0; j < 4; j++) {
        int n = base + j;
        if (n >= N) break;
        float4 acc = accs[j];
        acc.x += bv.x; acc.y += bv.y; acc.z += bv.z; acc.w += bv.w;
        ((float4*)g_xe)[n * 32 + l] = acc;
        float pi = acc.x * at[0]  + acc.y * at[1]  + acc.z * at[2]  + acc.w * at[3];
        float pj = acc.x * at2[0] + acc.y * at2[1] + acc.z * at2[2] + acc.w * at2[3];
#pragma unroll
        for (int o = 4; o; o >>= 1) {
            pi += __shfl_down_sync(0xffffffffu, pi, o, 8);
            pj += __shfl_down_sync(0xffffffffu, pj, o, 8);
        }
        if ((l & 7) == 0) { g_ai[n * 4 + h] = pi; g_aj[n * 4 + h] = pj; }
    }
}

__global__ __launch_bounds__(128) void node_h_kernel(const float* __restrict__ x,
                                                     const float* __restrict__ b_lin,
                                                     const float* __restrict__ att,
                                                     int N) {
    __shared__ float sx[4][4][D_];
    int w = threadIdx.x >> 5, l = threadIdx.x & 31;
    int base = blockIdx.x * 16 + w * 4;
    if (base >= N) return;
#pragma unroll
    for (int j = 0; j < 4; j++) {
        int n = min(base + j, N - 1);
        ((float4*)sx[w][j])[l] = ((const float4*)x)[n * 32 + l];
    }
    __syncwarp();
    float4 a0 = make_float4(0.f, 0.f, 0.f, 0.f), a1 = a0, a2 = a0, a3 = a0;
    const float4* Wt = (const float4*)g_WtH;
#pragma unroll 4
    for (int k = 0; k < D_; k++) {
        float4 wv = Wt[k * 32 + l];
        float s0 = sx[w][0][k], s1 = sx[w][1][k], s2 = sx[w][2][k], s3 = sx[w][3][k];
        a0.x = fmaf(s0, wv.x, a0.x); a0.y = fmaf(s0, wv.y, a0.y);
        a0.z = fmaf(s0, wv.z, a0.z); a0.w = fmaf(s0, wv.w, a0.w);
        a1.x = fmaf(s1, wv.x, a1.x); a1.y = fmaf(s1, wv.y, a1.y);
        a1.z = fmaf(s1, wv.z, a1.z); a1.w = fmaf(s1, wv.w, a1.w);
        a2.x = fmaf(s2, wv.x, a2.x); a2.y = fmaf(s2, wv.y, a2.y);
        a2.z = fmaf(s2, wv.z, a2.z); a2.w = fmaf(s2, wv.w, a2.w);
        a3.x = fmaf(s3, wv.x, a3.x); a3.y = fmaf(s3, wv.y, a3.y);
        a3.z = fmaf(s3, wv.z, a3.z); a3.w = fmaf(s3, wv.w, a3.w);
    }
    // hoisted bias: hb = proj(expmap0(b_lin_h)), y2 = ||hb||^2 (node-independent)
    float4 bvv = ((const float4*)b_lin)[l];
    float nb = fmaxf(sqrtf(wsum(d4(bvv, bvv))), MINNORM);
    float4 hb = f4s(bvv, tanhf(nb) / nb);
    projw(hb);
    float y2 = wsum(d4(hb, hb));

    float4 accs[4] = {a0, a1, a2, a3};
    int h = l >> 3, j0 = (l & 7) * 4;
    const float* at  = att + h * 64 + j0;
    const float* at2 = at + 32;
#pragma unroll
    for (int j = 0; j < 4; j++) {
        int n = base + j;
        if (n >= N) break;
        float4 xv = ((float4*)sx[w][j])[l];
        float n_x = fmaxf(sqrtf(wsum(d4(xv, xv))), MINNORM);
        float4 acc = accs[j];
        float n_mx = fmaxf(sqrtf(wsum(d4(acc, acc))), MINNORM);
        float f = tanhf(n_mx / n_x * atanhc(n_x)) / n_mx;
        float4 mv = f4s(acc, f);
        projw(mv);
        float x2 = wsum(d4(mv, mv));
        float xy = wsum(d4(mv, hb));
        float A = 1.f + 2.f * xy + y2, B = 1.f - x2;
        float den = fmaxf(1.f + 2.f * xy + x2 * y2, MINNORM);
        float4 xh = f4s(f4axby(A, mv, B, hb), 1.f / den);
        projw(xh);
        ((float4*)g_xh)[n * 32 + l] = xh;
        float x2f = wsum(d4(xh, xh));
        if (l == 0) g_x2[n] = x2f;
        float nxh = fmaxf(sqrtf(x2f), MINNORM);
        float4 lx = f4s(xh, atanhc(nxh) / nxh);
        ((float4*)g_lx)[n * 32 + l] = lx;
        float pi = lx.x * at[0]  + lx.y * at[1]  + lx.z * at[2]  + lx.w * at[3];
        float pj = lx.x * at2[0] + lx.y * at2[1] + lx.z * at2[2] + lx.w * at2[3];
#pragma unroll
        for (int o = 4; o; o >>= 1) {
            pi += __shfl_down_sync(0xffffffffu, pi, o, 8);
            pj += __shfl_down_sync(0xffffffffu, pj, o, 8);
        }
        if ((l & 7) == 0) { g_hi[n * 4 + h] = pi; g_hj[n * 4 + h] = pj; }
    }
}

// ---------------- fused edge + finalize: warp per destination node ----------------
__global__ __launch_bounds__(256) void fused_edge_kernel(const float* __restrict__ b_e,
                                                         const float* __restrict__ b_h,
                                                         const float* __restrict__ att_hf,
                                                         const float* __restrict__ att_ef,
                                                         float* __restrict__ out, int N) {
    int w = (blockIdx.x * blockDim.x + threadIdx.x) >> 5;
    int l = threadIdx.x & 31;
    if (w >= N) return;
    int dn = w;
    int beg = g_start[dn], end = g_start[dn + 1];

    float4 xd  = ((const float4*)g_xh)[dn * 32 + l];
    float  x2d = g_x2[dn];
    float  ai_l = (l < 4) ? g_ai[dn * 4 + l] : 0.f;
    float  hi_l = (l < 4) ? g_hi[dn * 4 + l] : 0.f;

    // Pass A: hyperbolic distances + euclidean logits, local exp-sums
    float sum_d = 0.f, sum_e = 0.f;
    for (int k = beg; k < end; k++) {
        int s = g_csrc[k];
        float4 xs = ((const float4*)g_xh)[s * 32 + l];
        float xy = wsum(d4(xd, xs));
        float y2 = g_x2[s];
        float A = 1.f - 2.f * xy + y2, B = 1.f - x2d;
        float den = fmaxf(1.f - 2.f * xy + x2d * y2, MINNORM);
        float num2 = fmaxf(A * A * x2d + B * B * y2 - 2.f * A * B * xy, 0.f);
        float dd = 2.f * atanhc(sqrtf(num2) / den);
        if (l == 0) g_de[k] = dd;
        sum_d += expf(dd);
        if (l < 4) {
            float le = lrelu(ai_l + g_aj[s * 4 + l]);
            g_le[k * 4 + l] = le;
            sum_e += expf(le);
        }
    }

    // Pass B: distance softmax -> hyperbolic logits, local exp-sums
    float sum_h = 0.f;
    float inv_sd = 1.f / (sum_d + 1e-16f);
    for (int k = beg; k < end; k++) {
        if (l < 4) {
            int s = g_csrc[k];
            float dsm = expf(g_de[k]) * inv_sd;
            float a = lrelu((hi_l + g_hj[s * 4 + l]) * dsm);
            g_ah[k * 4 + l] = a;
            sum_h += expf(a);
        }
    }

    int h = l >> 3;
    float se = __shfl_sync(0xffffffffu, sum_e, h);
    float sh = __shfl_sync(0xffffffffu, sum_h, h);
    float inv_se = 1.f / (se + 1e-16f);
    float inv_sh = 1.f / (sh + 1e-16f);

    // Pass C: weighted aggregation in registers
    float4 acc_e = make_float4(0.f, 0.f, 0.f, 0.f);
    float4 acc_h = make_float4(0.f, 0.f, 0.f, 0.f);
    for (int k = beg; k < end; k++) {
        int s = g_csrc[k];
        float we = expf(g_le[k * 4 + h]) * inv_se;
        float wh = expf(g_ah[k * 4 + h]) * inv_sh;
        float4 xs = ((const float4*)g_xe)[s * 32 + l];
        float4 ls = ((const float4*)g_lx)[s * 32 + l];
        acc_e.x = fmaf(we, xs.x, acc_e.x); acc_e.y = fmaf(we, xs.y, acc_e.y);
        acc_e.z = fmaf(we, xs.z, acc_e.z); acc_e.w = fmaf(we, xs.w, acc_e.w);
        acc_h.x = fmaf(wh, ls.x, acc_h.x); acc_h.y = fmaf(wh, ls.y, acc_h.y);
        acc_h.z = fmaf(wh, ls.z, acc_h.z); acc_h.w = fmaf(wh, ls.w, acc_h.w);
    }

    // ---- Finalize (in registers) ----
    int n = dn;
    float4 be = ((const float4*)b_e)[l];
    float4 eo = make_float4(fmaxf(acc_e.x + be.x, 0.f), fmaxf(acc_e.y + be.y, 0.f),
                            fmaxf(acc_e.z + be.z, 0.f), fmaxf(acc_e.w + be.w, 0.f));
    float4 bh = ((const float4*)b_h)[l];
    float4 ot = make_float4(fmaxf(acc_h.x + bh.x, 0.f), fmaxf(acc_h.y + bh.y, 0.f),
                            fmaxf(acc_h.z + bh.z, 0.f), fmaxf(acc_h.w + bh.w, 0.f));
    float nt = fmaxf(sqrtf(wsum(d4(ot, ot))), MINNORM);
    float4 ho = f4s(ot, tanhf(nt) / nt);
    projw(ho);
    float ne = fmaxf(sqrtf(wsum(d4(eo, eo))), MINNORM);
    float4 ye = f4s(eo, tanhf(ne) / ne);
    projw(ye);
    float x2 = wsum(d4(ho, ho));
    float y2 = wsum(d4(ye, ye));
    float xy = wsum(d4(ho, ye));
    float A = 1.f - 2.f * xy + y2, B = 1.f - x2;
    float den = fmaxf(1.f - 2.f * xy + x2 * y2, MINNORM);
    float num2 = fmaxf(A * A * x2 + B * B * y2 - 2.f * A * B * xy, 0.f);
    float r = 2.f * atanhc(sqrtf(num2) / den) * att_hf[0];
    float ny = fmaxf(sqrtf(y2), MINNORM);
    float4 xe2 = f4s(ye, tanhf(r * atanhc(ny)) / ny);
    projw(xe2);
    float y2b = wsum(d4(xe2, xe2));
    float xyb = wsum(d4(ho, xe2));
    float A2 = 1.f + 2.f * xyb + y2b, B2 = 1.f - x2;
    float den2 = fmaxf(1.f + 2.f * xyb + x2 * y2b, MINNORM);
    float4 hf = f4s(f4axby(A2, ho, B2, xe2), 1.f / den2);
    projw(hf);
    float nho = fmaxf(sqrtf(x2), MINNORM);
    float4 lh = f4s(ho, atanhc(nho) / nho);
    float4 df = make_float4(lh.x - eo.x, lh.y - eo.y, lh.z - eo.z, lh.w - eo.w);
    float de = wsum(d4(df, df)) * att_ef[0];
    float4 ef = make_float4(eo.x + de * lh.x, eo.y + de * lh.y,
                            eo.z + de * lh.z, eo.w + de * lh.w);
    ((float4*)out)[n * 32 + l] = hf;
    ((float4*)out)[(size_t)N * 32 + n * 32 + l] = ef;
}

// ---------------- launch ----------------
extern "C" void kernel_launch(void* const* d_in, const int* in_sizes, int n_in,
                              void* d_out, int out_size) {
    const float* x_e      = (const float*)d_in[0];
    const float* x_h      = (const float*)d_in[1];
    const int*   ei       = (const int*)d_in[2];
    const float* W_e      = (const float*)d_in[3];
    const float* b_lin_e  = (const float*)d_in[4];
    const float* att_e    = (const float*)d_in[5];
    const float* b_e      = (const float*)d_in[6];
    const float* W_h      = (const float*)d_in[7];
    const float* b_lin_h  = (const float*)d_in[8];
    const float* att_h    = (const float*)d_in[9];
    const float* b_h      = (const float*)d_in[10];
    const float* att_hf   = (const float*)d_in[11];
    const float* att_ef   = (const float*)d_in[12];
    float* out = (float*)d_out;

    int N  = in_sizes[0] / D_;
    int E  = in_sizes[2] / 2;
    int EP = E + N;

    zero_kernel<<<(N + 255) / 256, 256>>>(N);
    transpose_kernel<<<(2 * D_ * D_ + 255) / 256, 256>>>(W_e, W_h);
    count_kernel<<<(EP + 255) / 256, 256>>>(ei, E, EP);
    node_e_kernel<<<(N + 15) / 16, 128>>>(x_e, b_lin_e, att_e, N);
    node_h_kernel<<<(N + 15) / 16, 128>>>(x_h, b_lin_h, att_h, N);
    scan_kernel<<<1, 1024>>>(N);
    scatter_kernel<<<(EP + 255) / 256, 256>>>(ei, E, EP);
    fused_edge_kernel<<<(N * 32 + 255) / 256, 256>>>(b_e, b_h, att_hf, att_ef, out, N);
}

// round 3
// speedup vs baseline: 2.1179x; 1.1493x over previous
#include <cuda_runtime.h>
#include <math.h>

#define D_ 128
#define NMAX 50016
#define EPMAX 550032
#define MAXN 0.99999f
#define MINNORM 1e-15f

// ---------------- scratch ----------------
__device__ float g_xe[NMAX * D_];
__device__ float g_xh[NMAX * D_];
__device__ float g_lx[NMAX * D_];
__device__ float g_ai[NMAX * 4];
__device__ float g_aj[NMAX * 4];
__device__ float g_hi[NMAX * 4];
__device__ float g_hj[NMAX * 4];
__device__ float g_x2[NMAX];
__device__ float g_de[EPMAX];       // exp(distance)
__device__ float g_le[EPMAX * 4];   // exp(euclid logit)
__device__ float g_ah[EPMAX * 4];   // exp(hyperbolic logit)
__device__ float g_WtE[D_ * D_];
__device__ float g_WtH[D_ * D_];
__device__ int   g_deg[NMAX];
__device__ int   g_cur[NMAX];
__device__ int   g_start[NMAX + 1];
__device__ int   g_csrc[EPMAX];

// ---------------- helpers ----------------
__device__ __forceinline__ float atanhc(float x) {
    x = fminf(fmaxf(x, -1.0f + 1e-7f), 1.0f - 1e-7f);
    return atanhf(x);
}
__device__ __forceinline__ float wsum(float v) {
#pragma unroll
    for (int o = 16; o; o >>= 1) v += __shfl_xor_sync(0xffffffffu, v, o);
    return v;
}
__device__ __forceinline__ float d4(float4 a, float4 b) {
    return a.x * b.x + a.y * b.y + a.z * b.z + a.w * b.w;
}
__device__ __forceinline__ float4 f4s(float4 a, float s) {
    return make_float4(a.x * s, a.y * s, a.z * s, a.w * s);
}
__device__ __forceinline__ float4 f4axby(float a, float4 x, float b, float4 y) {
    return make_float4(a * x.x + b * y.x, a * x.y + b * y.y,
                       a * x.z + b * y.z, a * x.w + b * y.w);
}
__device__ __forceinline__ void projw(float4 &v) {
    float n = fmaxf(sqrtf(wsum(d4(v, v))), MINNORM);
    if (n > MAXN) {
        float s = MAXN / n;
        v.x *= s; v.y *= s; v.z *= s; v.w *= s;
    }
}
__device__ __forceinline__ float lrelu(float v) { return v >= 0.f ? v : 0.2f * v; }

// packed f32x2 helpers (Blackwell FFMA2)
__device__ __forceinline__ void ffma2(unsigned long long &acc,
                                      unsigned long long a, unsigned long long b) {
    asm("fma.rn.f32x2 %0, %1, %2, %3;" : "=l"(acc) : "l"(a), "l"(b), "l"(acc));
}
__device__ __forceinline__ unsigned long long pack2(float s) {
    unsigned u = __float_as_uint(s);
    unsigned long long r;
    asm("mov.b64 %0, {%1, %1};" : "=l"(r) : "r"(u));
    return r;
}
__device__ __forceinline__ float4 unpack4(unsigned long long lo, unsigned long long hi) {
    float4 v;
    asm("mov.b64 {%0, %1}, %2;" : "=f"(v.x), "=f"(v.y) : "l"(lo));
    asm("mov.b64 {%0, %1}, %2;" : "=f"(v.z), "=f"(v.w) : "l"(hi));
    return v;
}

// ---------------- CSR build ----------------
__global__ __launch_bounds__(256) void zero_kernel(int N) {
    int i = blockIdx.x * blockDim.x + threadIdx.x;
    if (i < N) { g_deg[i] = 0; g_cur[i] = 0; }
}

__global__ __launch_bounds__(256) void count_kernel(const int* __restrict__ ei, int E, int EP) {
    int e = blockIdx.x * blockDim.x + threadIdx.x;
    if (e >= EP) return;
    int dn = (e < E) ? ei[E + e] : (e - E);
    atomicAdd(&g_deg[dn], 1);
}

__global__ __launch_bounds__(1024) void scan_kernel(int N) {
    __shared__ int sums[1024];
    int t = threadIdx.x;
    int chunk = (N + 1023) >> 10;
    int b = t * chunk, e = min(b + chunk, N);
    int own = 0;
    for (int i = b; i < e; i++) own += g_deg[i];
    sums[t] = own;
    __syncthreads();
#pragma unroll
    for (int d = 1; d < 1024; d <<= 1) {
        int v = (t >= d) ? sums[t - d] : 0;
        __syncthreads();
        sums[t] += v;
        __syncthreads();
    }
    int off = sums[t] - own;
    for (int i = b; i < e; i++) { g_start[i] = off; off += g_deg[i]; }
    if (b < N && e == N) g_start[N] = off;
}

__global__ __launch_bounds__(256) void scatter_kernel(const int* __restrict__ ei, int E, int EP) {
    int e = blockIdx.x * blockDim.x + threadIdx.x;
    if (e >= EP) return;
    int s, dn;
    if (e < E) { s = ei[e]; dn = ei[E + e]; } else { s = dn = e - E; }
    int pos = atomicAdd(&g_cur[dn], 1);
    g_csrc[g_start[dn] + pos] = s;
}

__global__ __launch_bounds__(256) void transpose_kernel(const float* __restrict__ We,
                                                        const float* __restrict__ Wh) {
    int i = blockIdx.x * blockDim.x + threadIdx.x;
    if (i >= 2 * D_ * D_) return;
    int m = i >> 14;
    int k = (i >> 7) & 127;
    int c = i & 127;
    if (m == 0) g_WtE[k * D_ + c] = We[c * D_ + k];
    else        g_WtH[k * D_ + c] = Wh[c * D_ + k];
}

// ---------------- node kernels: 8 nodes/warp, packed f32x2 GEMM ----------------
__global__ __launch_bounds__(128) void node_e_kernel(const float* __restrict__ x,
                                                     const float* __restrict__ b_lin,
                                                     const float* __restrict__ att,
                                                     int N) {
    __shared__ float sx[4][8][D_];
    int w = threadIdx.x >> 5, l = threadIdx.x & 31;
    int base = blockIdx.x * 32 + w * 8;
    if (base >= N) return;
#pragma unroll
    for (int j = 0; j < 8; j++) {
        int n = min(base + j, N - 1);
        ((float4*)sx[w][j])[l] = ((const float4*)x)[n * 32 + l];
    }
    __syncwarp();
    unsigned long long acc[8][2];
#pragma unroll
    for (int j = 0; j < 8; j++) { acc[j][0] = 0ull; acc[j][1] = 0ull; }
    const ulonglong2* Wt = (const ulonglong2*)g_WtE;
#pragma unroll 2
    for (int k = 0; k < D_; k++) {
        ulonglong2 wv = Wt[k * 32 + l];
#pragma unroll
        for (int j = 0; j < 8; j++) {
            unsigned long long ss = pack2(sx[w][j][k]);
            ffma2(acc[j][0], ss, wv.x);
            ffma2(acc[j][1], ss, wv.y);
        }
    }
    float4 bv = ((const float4*)b_lin)[l];
    int h = l >> 3, j0 = (l & 7) * 4;
    const float* at  = att + h * 64 + j0;
    const float* at2 = at + 32;
#pragma unroll
    for (int j = 0; j < 8; j++) {
        int n = base + j;
        if (n >= N) break;
        float4 a = unpack4(acc[j][0], acc[j][1]);
        a.x += bv.x; a.y += bv.y; a.z += bv.z; a.w += bv.w;
        ((float4*)g_xe)[n * 32 + l] = a;
        float pi = a.x * at[0]  + a.y * at[1]  + a.z * at[2]  + a.w * at[3];
        float pj = a.x * at2[0] + a.y * at2[1] + a.z * at2[2] + a.w * at2[3];
#pragma unroll
        for (int o = 4; o; o >>= 1) {
            pi += __shfl_down_sync(0xffffffffu, pi, o, 8);
            pj += __shfl_down_sync(0xffffffffu, pj, o, 8);
        }
        if ((l & 7) == 0) { g_ai[n * 4 + h] = pi; g_aj[n * 4 + h] = pj; }
    }
}

__global__ __launch_bounds__(128) void node_h_kernel(const float* __restrict__ x,
                                                     const float* __restrict__ b_lin,
                                                     const float* __restrict__ att,
                                                     int N) {
    __shared__ float sx[4][8][D_];
    int w = threadIdx.x >> 5, l = threadIdx.x & 31;
    int base = blockIdx.x * 32 + w * 8;
    if (base >= N) return;
#pragma unroll
    for (int j = 0; j < 8; j++) {
        int n = min(base + j, N - 1);
        ((float4*)sx[w][j])[l] = ((const float4*)x)[n * 32 + l];
    }
    __syncwarp();
    unsigned long long acc[8][2];
#pragma unroll
    for (int j = 0; j < 8; j++) { acc[j][0] = 0ull; acc[j][1] = 0ull; }
    const ulonglong2* Wt = (const ulonglong2*)g_WtH;
#pragma unroll 2
    for (int k = 0; k < D_; k++) {
        ulonglong2 wv = Wt[k * 32 + l];
#pragma unroll
        for (int j = 0; j < 8; j++) {
            unsigned long long ss = pack2(sx[w][j][k]);
            ffma2(acc[j][0], ss, wv.x);
            ffma2(acc[j][1], ss, wv.y);
        }
    }
    // hoisted bias point hb = proj(expmap0(b_lin_h))
    float4 bvv = ((const float4*)b_lin)[l];
    float nb = fmaxf(sqrtf(wsum(d4(bvv, bvv))), MINNORM);
    float4 hb = f4s(bvv, tanhf(nb) / nb);
    projw(hb);
    float y2 = wsum(d4(hb, hb));

    int h = l >> 3, j0 = (l & 7) * 4;
    const float* at  = att + h * 64 + j0;
    const float* at2 = at + 32;
#pragma unroll
    for (int j = 0; j < 8; j++) {
        int n = base + j;
        if (n >= N) break;
        float4 xv = ((float4*)sx[w][j])[l];
        float n_x = fmaxf(sqrtf(wsum(d4(xv, xv))), MINNORM);
        float4 mx = unpack4(acc[j][0], acc[j][1]);
        float n_mx = fmaxf(sqrtf(wsum(d4(mx, mx))), MINNORM);
        float f = tanhf(n_mx / n_x * atanhc(n_x)) / n_mx;
        float4 mv = f4s(mx, f);
        projw(mv);
        float x2 = wsum(d4(mv, mv));
        float xy = wsum(d4(mv, hb));
        float A = 1.f + 2.f * xy + y2, B = 1.f - x2;
        float den = fmaxf(1.f + 2.f * xy + x2 * y2, MINNORM);
        float4 xh = f4s(f4axby(A, mv, B, hb), 1.f / den);
        projw(xh);
        ((float4*)g_xh)[n * 32 + l] = xh;
        float x2f = wsum(d4(xh, xh));
        if (l == 0) g_x2[n] = x2f;
        float nxh = fmaxf(sqrtf(x2f), MINNORM);
        float4 lx = f4s(xh, atanhc(nxh) / nxh);
        ((float4*)g_lx)[n * 32 + l] = lx;
        float pi = lx.x * at[0]  + lx.y * at[1]  + lx.z * at[2]  + lx.w * at[3];
        float pj = lx.x * at2[0] + lx.y * at2[1] + lx.z * at2[2] + lx.w * at2[3];
#pragma unroll
        for (int o = 4; o; o >>= 1) {
            pi += __shfl_down_sync(0xffffffffu, pi, o, 8);
            pj += __shfl_down_sync(0xffffffffu, pj, o, 8);
        }
        if ((l & 7) == 0) { g_hi[n * 4 + h] = pi; g_hj[n * 4 + h] = pj; }
    }
}

// ---------------- fused edge + finalize: warp per destination node ----------------
__global__ __launch_bounds__(256) void fused_edge_kernel(const float* __restrict__ b_e,
                                                         const float* __restrict__ b_h,
                                                         const float* __restrict__ att_hf,
                                                         const float* __restrict__ att_ef,
                                                         float* __restrict__ out, int N) {
    int w = (blockIdx.x * blockDim.x + threadIdx.x) >> 5;
    int l = threadIdx.x & 31;
    if (w >= N) return;
    int dn = w;
    int beg = g_start[dn], end = g_start[dn + 1];

    float4 xd  = ((const float4*)g_xh)[dn * 32 + l];
    float  x2d = g_x2[dn];
    float  ai_l = (l < 4) ? g_ai[dn * 4 + l] : 0.f;
    float  hi_l = (l < 4) ? g_hi[dn * 4 + l] : 0.f;

    // ---- Pass A: distances + euclid logits (4-edge batches) ----
    float sum_d = 0.f;   // lanes 0..3 hold partials -> wsum later
    float sum_e = 0.f;   // lane l<4 holds head-l sum
    int k = beg;
    for (; k + 4 <= end; k += 4) {
        int s0 = g_csrc[k + 0], s1 = g_csrc[k + 1];
        int s2 = g_csrc[k + 2], s3 = g_csrc[k + 3];
        float4 v0 = ((const float4*)g_xh)[s0 * 32 + l];
        float4 v1 = ((const float4*)g_xh)[s1 * 32 + l];
        float4 v2 = ((const float4*)g_xh)[s2 * 32 + l];
        float4 v3 = ((const float4*)g_xh)[s3 * 32 + l];
        float p0 = d4(xd, v0), p1 = d4(xd, v1), p2 = d4(xd, v2), p3 = d4(xd, v3);
#pragma unroll
        for (int o = 16; o; o >>= 1) {
            p0 += __shfl_xor_sync(0xffffffffu, p0, o);
            p1 += __shfl_xor_sync(0xffffffffu, p1, o);
            p2 += __shfl_xor_sync(0xffffffffu, p2, o);
            p3 += __shfl_xor_sync(0xffffffffu, p3, o);
        }
        if (l < 4) {
            int ssel = (l == 0) ? s0 : (l == 1) ? s1 : (l == 2) ? s2 : s3;
            float pp = (l == 0) ? p0 : (l == 1) ? p1 : (l == 2) ? p2 : p3;
            float yy = g_x2[ssel];
            float A = 1.f - 2.f * pp + yy, B = 1.f - x2d;
            float den = fmaxf(1.f - 2.f * pp + x2d * yy, MINNORM);
            float num2 = fmaxf(A * A * x2d + B * B * yy - 2.f * A * B * pp, 0.f);
            float edd = expf(2.f * atanhc(sqrtf(num2) / den));
            g_de[k + l] = edd;
            sum_d += edd;
            float e0 = expf(lrelu(ai_l + g_aj[s0 * 4 + l]));
            float e1 = expf(lrelu(ai_l + g_aj[s1 * 4 + l]));
            float e2 = expf(lrelu(ai_l + g_aj[s2 * 4 + l]));
            float e3 = expf(lrelu(ai_l + g_aj[s3 * 4 + l]));
            g_le[(k + 0) * 4 + l] = e0;
            g_le[(k + 1) * 4 + l] = e1;
            g_le[(k + 2) * 4 + l] = e2;
            g_le[(k + 3) * 4 + l] = e3;
            sum_e += e0 + e1 + e2 + e3;
        }
    }
    for (; k < end; k++) {
        int s = g_csrc[k];
        float4 xs = ((const float4*)g_xh)[s * 32 + l];
        float xy = wsum(d4(xd, xs));
        float yy = g_x2[s];
        float A = 1.f - 2.f * xy + yy, B = 1.f - x2d;
        float den = fmaxf(1.f - 2.f * xy + x2d * yy, MINNORM);
        float num2 = fmaxf(A * A * x2d + B * B * yy - 2.f * A * B * xy, 0.f);
        float edd = expf(2.f * atanhc(sqrtf(num2) / den));
        if (l == 0) { g_de[k] = edd; sum_d += edd; }
        if (l < 4) {
            float le = expf(lrelu(ai_l + g_aj[s * 4 + l]));
            g_le[k * 4 + l] = le;
            sum_e += le;
        }
    }
    float inv_sd = 1.f / (wsum(sum_d) + 1e-16f);

    // ---- Pass B: hyperbolic logits (lanes 0..3, 4-edge batches) ----
    float sum_h = 0.f;
    k = beg;
    for (; k + 4 <= end; k += 4) {
        if (l < 4) {
            int s0 = g_csrc[k + 0], s1 = g_csrc[k + 1];
            int s2 = g_csrc[k + 2], s3 = g_csrc[k + 3];
            float d0 = g_de[k + 0] * inv_sd, d1 = g_de[k + 1] * inv_sd;
            float d2 = g_de[k + 2] * inv_sd, d3 = g_de[k + 3] * inv_sd;
            float a0 = expf(lrelu((hi_l + g_hj[s0 * 4 + l]) * d0));
            float a1 = expf(lrelu((hi_l + g_hj[s1 * 4 + l]) * d1));
            float a2 = expf(lrelu((hi_l + g_hj[s2 * 4 + l]) * d2));
            float a3 = expf(lrelu((hi_l + g_hj[s3 * 4 + l]) * d3));
            g_ah[(k + 0) * 4 + l] = a0;
            g_ah[(k + 1) * 4 + l] = a1;
            g_ah[(k + 2) * 4 + l] = a2;
            g_ah[(k + 3) * 4 + l] = a3;
            sum_h += a0 + a1 + a2 + a3;
        }
    }
    for (; k < end; k++) {
        if (l < 4) {
            int s = g_csrc[k];
            float dsm = g_de[k] * inv_sd;
            float a = expf(lrelu((hi_l + g_hj[s * 4 + l]) * dsm));
            g_ah[k * 4 + l] = a;
            sum_h += a;
        }
    }

    int h = l >> 3;
    float se = __shfl_sync(0xffffffffu, sum_e, h);
    float sh = __shfl_sync(0xffffffffu, sum_h, h);
    float inv_se = 1.f / (se + 1e-16f);
    float inv_sh = 1.f / (sh + 1e-16f);

    // ---- Pass C: weighted aggregation (2-edge batches for load MLP) ----
    float4 acc_e = make_float4(0.f, 0.f, 0.f, 0.f);
    float4 acc_h = make_float4(0.f, 0.f, 0.f, 0.f);
    k = beg;
    for (; k + 2 <= end; k += 2) {
        int s0 = g_csrc[k], s1 = g_csrc[k + 1];
        float we0 = g_le[k * 4 + h] * inv_se;
        float wh0 = g_ah[k * 4 + h] * inv_sh;
        float we1 = g_le[(k + 1) * 4 + h] * inv_se;
        float wh1 = g_ah[(k + 1) * 4 + h] * inv_sh;
        float4 xs0 = ((const float4*)g_xe)[s0 * 32 + l];
        float4 ls0 = ((const float4*)g_lx)[s0 * 32 + l];
        float4 xs1 = ((const float4*)g_xe)[s1 * 32 + l];
        float4 ls1 = ((const float4*)g_lx)[s1 * 32 + l];
        acc_e.x = fmaf(we0, xs0.x, fmaf(we1, xs1.x, acc_e.x));
        acc_e.y = fmaf(we0, xs0.y, fmaf(we1, xs1.y, acc_e.y));
        acc_e.z = fmaf(we0, xs0.z, fmaf(we1, xs1.z, acc_e.z));
        acc_e.w = fmaf(we0, xs0.w, fmaf(we1, xs1.w, acc_e.w));
        acc_h.x = fmaf(wh0, ls0.x, fmaf(wh1, ls1.x, acc_h.x));
        acc_h.y = fmaf(wh0, ls0.y, fmaf(wh1, ls1.y, acc_h.y));
        acc_h.z = fmaf(wh0, ls0.z, fmaf(wh1, ls1.z, acc_h.z));
        acc_h.w = fmaf(wh0, ls0.w, fmaf(wh1, ls1.w, acc_h.w));
    }
    for (; k < end; k++) {
        int s = g_csrc[k];
        float we = g_le[k * 4 + h] * inv_se;
        float wh = g_ah[k * 4 + h] * inv_sh;
        float4 xs = ((const float4*)g_xe)[s * 32 + l];
        float4 ls = ((const float4*)g_lx)[s * 32 + l];
        acc_e.x = fmaf(we, xs.x, acc_e.x); acc_e.y = fmaf(we, xs.y, acc_e.y);
        acc_e.z = fmaf(we, xs.z, acc_e.z); acc_e.w = fmaf(we, xs.w, acc_e.w);
        acc_h.x = fmaf(wh, ls.x, acc_h.x); acc_h.y = fmaf(wh, ls.y, acc_h.y);
        acc_h.z = fmaf(wh, ls.z, acc_h.z); acc_h.w = fmaf(wh, ls.w, acc_h.w);
    }

    // ---- Finalize (in registers) ----
    int n = dn;
    float4 be = ((const float4*)b_e)[l];
    float4 eo = make_float4(fmaxf(acc_e.x + be.x, 0.f), fmaxf(acc_e.y + be.y, 0.f),
                            fmaxf(acc_e.z + be.z, 0.f), fmaxf(acc_e.w + be.w, 0.f));
    float4 bh = ((const float4*)b_h)[l];
    float4 ot = make_float4(fmaxf(acc_h.x + bh.x, 0.f), fmaxf(acc_h.y + bh.y, 0.f),
                            fmaxf(acc_h.z + bh.z, 0.f), fmaxf(acc_h.w + bh.w, 0.f));
    float nt = fmaxf(sqrtf(wsum(d4(ot, ot))), MINNORM);
    float4 ho = f4s(ot, tanhf(nt) / nt);
    projw(ho);
    float ne = fmaxf(sqrtf(wsum(d4(eo, eo))), MINNORM);
    float4 ye = f4s(eo, tanhf(ne) / ne);
    projw(ye);
    float x2 = wsum(d4(ho, ho));
    float y2 = wsum(d4(ye, ye));
    float xy = wsum(d4(ho, ye));
    float A = 1.f - 2.f * xy + y2, B = 1.f - x2;
    float den = fmaxf(1.f - 2.f * xy + x2 * y2, MINNORM);
    float num2 = fmaxf(A * A * x2 + B * B * y2 - 2.f * A * B * xy, 0.f);
    float r = 2.f * atanhc(sqrtf(num2) / den) * att_hf[0];
    float ny = fmaxf(sqrtf(y2), MINNORM);
    float4 xe2 = f4s(ye, tanhf(r * atanhc(ny)) / ny);
    projw(xe2);
    float y2b = wsum(d4(xe2, xe2));
    float xyb = wsum(d4(ho, xe2));
    float A2 = 1.f + 2.f * xyb + y2b, B2 = 1.f - x2;
    float den2 = fmaxf(1.f + 2.f * xyb + x2 * y2b, MINNORM);
    float4 hf = f4s(f4axby(A2, ho, B2, xe2), 1.f / den2);
    projw(hf);
    float nho = fmaxf(sqrtf(x2), MINNORM);
    float4 lh = f4s(ho, atanhc(nho) / nho);
    float4 df = make_float4(lh.x - eo.x, lh.y - eo.y, lh.z - eo.z, lh.w - eo.w);
    float de = wsum(d4(df, df)) * att_ef[0];
    float4 ef = make_float4(eo.x + de * lh.x, eo.y + de * lh.y,
                            eo.z + de * lh.z, eo.w + de * lh.w);
    ((float4*)out)[n * 32 + l] = hf;
    ((float4*)out)[(size_t)N * 32 + n * 32 + l] = ef;
}

// ---------------- launch ----------------
extern "C" void kernel_launch(void* const* d_in, const int* in_sizes, int n_in,
                              void* d_out, int out_size) {
    const float* x_e      = (const float*)d_in[0];
    const float* x_h      = (const float*)d_in[1];
    const int*   ei       = (const int*)d_in[2];
    const float* W_e      = (const float*)d_in[3];
    const float* b_lin_e  = (const float*)d_in[4];
    const float* att_e    = (const float*)d_in[5];
    const float* b_e      = (const float*)d_in[6];
    const float* W_h      = (const float*)d_in[7];
    const float* b_lin_h  = (const float*)d_in[8];
    const float* att_h    = (const float*)d_in[9];
    const float* b_h      = (const float*)d_in[10];
    const float* att_hf   = (const float*)d_in[11];
    const float* att_ef   = (const float*)d_in[12];
    float* out = (float*)d_out;

    int N  = in_sizes[0] / D_;
    int E  = in_sizes[2] / 2;
    int EP = E + N;

    zero_kernel<<<(N + 255) / 256, 256>>>(N);
    transpose_kernel<<<(2 * D_ * D_ + 255) / 256, 256>>>(W_e, W_h);
    count_kernel<<<(EP + 255) / 256, 256>>>(ei, E, EP);
    node_e_kernel<<<(N + 31) / 32, 128>>>(x_e, b_lin_e, att_e, N);
    node_h_kernel<<<(N + 31) / 32, 128>>>(x_h, b_lin_h, att_h, N);
    scan_kernel<<<1, 1024>>>(N);
    scatter_kernel<<<(EP + 255) / 256, 256>>>(ei, E, EP);
    fused_edge_kernel<<<(N * 32 + 255) / 256, 256>>>(b_e, b_h, att_hf, att_ef, out, N);
}

// round 4
// speedup vs baseline: 2.4676x; 1.1651x over previous
#include <cuda_runtime.h>
#include <math.h>

#define D_ 128
#define NMAX 50016
#define EPMAX 550032
#define MAXN 0.99999f
#define MINNORM 1e-15f

// ---------------- scratch ----------------
__device__ float g_xe[NMAX * D_];
__device__ float g_xh[NMAX * D_];
__device__ float g_lx[NMAX * D_];
__device__ float g_ai[NMAX * 4];
__device__ float g_aj[NMAX * 4];
__device__ float g_hi[NMAX * 4];
__device__ float g_hj[NMAX * 4];
__device__ float g_x2[NMAX];
__device__ float g_de[EPMAX];       // exp(distance)
__device__ float g_le[EPMAX * 4];   // exp(euclid logit)
__device__ float g_ah[EPMAX * 4];   // exp(hyperbolic logit)
__device__ float g_WtE[D_ * D_];
__device__ float g_WtH[D_ * D_];
__device__ int   g_deg[NMAX];
__device__ int   g_cur[NMAX];
__device__ int   g_start[NMAX + 1];
__device__ int   g_csrc[EPMAX];
__device__ int   g_bsum[256];

// ---------------- helpers ----------------
__device__ __forceinline__ float atanhc(float x) {
    x = fminf(fmaxf(x, -1.0f + 1e-7f), 1.0f - 1e-7f);
    return atanhf(x);
}
__device__ __forceinline__ float wsum(float v) {
#pragma unroll
    for (int o = 16; o; o >>= 1) v += __shfl_xor_sync(0xffffffffu, v, o);
    return v;
}
__device__ __forceinline__ float d4(float4 a, float4 b) {
    return a.x * b.x + a.y * b.y + a.z * b.z + a.w * b.w;
}
__device__ __forceinline__ float4 f4s(float4 a, float s) {
    return make_float4(a.x * s, a.y * s, a.z * s, a.w * s);
}
__device__ __forceinline__ float4 f4axby(float a, float4 x, float b, float4 y) {
    return make_float4(a * x.x + b * y.x, a * x.y + b * y.y,
                       a * x.z + b * y.z, a * x.w + b * y.w);
}
__device__ __forceinline__ float lrelu(float v) { return v >= 0.f ? v : 0.2f * v; }

// packed f32x2 helpers (Blackwell FFMA2)
__device__ __forceinline__ void ffma2(unsigned long long &acc,
                                      unsigned long long a, unsigned long long b) {
    asm("fma.rn.f32x2 %0, %1, %2, %3;" : "=l"(acc) : "l"(a), "l"(b), "l"(acc));
}
__device__ __forceinline__ unsigned long long pack2(float s) {
    unsigned u = __float_as_uint(s);
    unsigned long long r;
    asm("mov.b64 %0, {%1, %1};" : "=l"(r) : "r"(u));
    return r;
}
__device__ __forceinline__ float4 unpack4(unsigned long long lo, unsigned long long hi) {
    float4 v;
    asm("mov.b64 {%0, %1}, %2;" : "=f"(v.x), "=f"(v.y) : "l"(lo));
    asm("mov.b64 {%0, %1}, %2;" : "=f"(v.z), "=f"(v.w) : "l"(hi));
    return v;
}

// ---------------- CSR build ----------------
__global__ __launch_bounds__(256) void zero_kernel(int N) {
    int i = blockIdx.x * blockDim.x + threadIdx.x;
    if (i < N) g_deg[i] = 0;
}

__global__ __launch_bounds__(256) void count_kernel(const int* __restrict__ ei, int E, int EP) {
    int e = blockIdx.x * blockDim.x + threadIdx.x;
    if (e >= EP) return;
    int dn = (e < E) ? ei[E + e] : (e - E);
    atomicAdd(&g_deg[dn], 1);
}

// phase 1: per-block inclusive scan of degrees -> exclusive starts (local) + block sums
__global__ __launch_bounds__(256) void scan1_kernel(int N) {
    __shared__ int sm[256];
    int i = blockIdx.x * 256 + threadIdx.x;
    int v = (i < N) ? g_deg[i] : 0;
    sm[threadIdx.x] = v;
    __syncthreads();
#pragma unroll
    for (int d = 1; d < 256; d <<= 1) {
        int t = (threadIdx.x >= d) ? sm[threadIdx.x - d] : 0;
        __syncthreads();
        sm[threadIdx.x] += t;
        __syncthreads();
    }
    if (i < N) g_start[i] = sm[threadIdx.x] - v;
    if (threadIdx.x == 255) g_bsum[blockIdx.x] = sm[255];
}

// phase 2: exclusive scan of block sums (single block)
__global__ __launch_bounds__(256) void scan2_kernel(int nb) {
    __shared__ int sm[256];
    int v = (threadIdx.x < nb) ? g_bsum[threadIdx.x] : 0;
    sm[threadIdx.x] = v;
    __syncthreads();
#pragma unroll
    for (int d = 1; d < 256; d <<= 1) {
        int t = (threadIdx.x >= d) ? sm[threadIdx.x - d] : 0;
        __syncthreads();
        sm[threadIdx.x] += t;
        __syncthreads();
    }
    g_bsum[threadIdx.x] = sm[threadIdx.x] - v;
}

// phase 3: add block offsets, reset cursors, set sentinel
__global__ __launch_bounds__(256) void scan3_kernel(int N, int EP) {
    int i = blockIdx.x * 256 + threadIdx.x;
    if (i < N) { g_start[i] += g_bsum[i >> 8]; g_cur[i] = 0; }
    if (i == 0) g_start[N] = EP;
}

__global__ __launch_bounds__(256) void scatter_kernel(const int* __restrict__ ei, int E, int EP) {
    int e = blockIdx.x * blockDim.x + threadIdx.x;
    if (e >= EP) return;
    int s, dn;
    if (e < E) { s = ei[e]; dn = ei[E + e]; } else { s = dn = e - E; }
    int pos = atomicAdd(&g_cur[dn], 1);
    g_csrc[g_start[dn] + pos] = s;
}

__global__ __launch_bounds__(256) void transpose_kernel(const float* __restrict__ We,
                                                        const float* __restrict__ Wh) {
    int i = blockIdx.x * blockDim.x + threadIdx.x;
    if (i >= 2 * D_ * D_) return;
    int m = i >> 14;
    int k = (i >> 7) & 127;
    int c = i & 127;
    if (m == 0) g_WtE[k * D_ + c] = We[c * D_ + k];
    else        g_WtH[k * D_ + c] = Wh[c * D_ + k];
}

// ---------------- node kernels: 8 nodes/warp, grid-stride over 32-node groups ----------------
__global__ __launch_bounds__(128) void node_e_kernel(const float* __restrict__ x,
                                                     const float* __restrict__ b_lin,
                                                     const float* __restrict__ att,
                                                     int N, int ngrp) {
    __shared__ float sx[4][8][D_];
    int w = threadIdx.x >> 5, l = threadIdx.x & 31;
    int h = l >> 3, j0 = (l & 7) * 4;
    const float* at  = att + h * 64 + j0;
    const float* at2 = at + 32;
    float4 bv = ((const float4*)b_lin)[l];
    for (int grp = blockIdx.x; grp < ngrp; grp += gridDim.x) {
        int base = grp * 32 + w * 8;
        if (base < N) {
#pragma unroll
            for (int j = 0; j < 8; j++) {
                int n = min(base + j, N - 1);
                ((float4*)sx[w][j])[l] = ((const float4*)x)[n * 32 + l];
            }
            __syncwarp();
            unsigned long long acc[8][2];
#pragma unroll
            for (int j = 0; j < 8; j++) { acc[j][0] = 0ull; acc[j][1] = 0ull; }
            const ulonglong2* Wt = (const ulonglong2*)g_WtE;
#pragma unroll 2
            for (int k = 0; k < D_; k++) {
                ulonglong2 wv = Wt[k * 32 + l];
#pragma unroll
                for (int j = 0; j < 8; j++) {
                    unsigned long long ss = pack2(sx[w][j][k]);
                    ffma2(acc[j][0], ss, wv.x);
                    ffma2(acc[j][1], ss, wv.y);
                }
            }
#pragma unroll
            for (int j = 0; j < 8; j++) {
                int n = base + j;
                if (n >= N) break;
                float4 a = unpack4(acc[j][0], acc[j][1]);
                a.x += bv.x; a.y += bv.y; a.z += bv.z; a.w += bv.w;
                ((float4*)g_xe)[n * 32 + l] = a;
                float pi = a.x * at[0]  + a.y * at[1]  + a.z * at[2]  + a.w * at[3];
                float pj = a.x * at2[0] + a.y * at2[1] + a.z * at2[2] + a.w * at2[3];
#pragma unroll
                for (int o = 4; o; o >>= 1) {
                    pi += __shfl_down_sync(0xffffffffu, pi, o, 8);
                    pj += __shfl_down_sync(0xffffffffu, pj, o, 8);
                }
                if ((l & 7) == 0) { g_ai[n * 4 + h] = pi; g_aj[n * 4 + h] = pj; }
            }
            __syncwarp();
        }
    }
}

__global__ __launch_bounds__(128) void node_h_kernel(const float* __restrict__ x,
                                                     const float* __restrict__ b_lin,
                                                     const float* __restrict__ att,
                                                     int N, int ngrp) {
    __shared__ float sx[4][8][D_];
    int w = threadIdx.x >> 5, l = threadIdx.x & 31;
    int h = l >> 3, j0 = (l & 7) * 4;
    const float* at  = att + h * 64 + j0;
    const float* at2 = at + 32;
    // hoisted bias point hb = proj(expmap0(b_lin_h)); scalar norms
    float4 bvv = ((const float4*)b_lin)[l];
    float nb = fmaxf(sqrtf(wsum(d4(bvv, bvv))), MINNORM);
    float nhb = fminf(tanhf(nb), MAXN);
    float4 hb = f4s(bvv, nhb / nb);
    float y2 = nhb * nhb;

    for (int grp = blockIdx.x; grp < ngrp; grp += gridDim.x) {
        int base = grp * 32 + w * 8;
        if (base < N) {
#pragma unroll
            for (int j = 0; j < 8; j++) {
                int n = min(base + j, N - 1);
                ((float4*)sx[w][j])[l] = ((const float4*)x)[n * 32 + l];
            }
            __syncwarp();
            unsigned long long acc[8][2];
#pragma unroll
            for (int j = 0; j < 8; j++) { acc[j][0] = 0ull; acc[j][1] = 0ull; }
            const ulonglong2* Wt = (const ulonglong2*)g_WtH;
#pragma unroll 2
            for (int k = 0; k < D_; k++) {
                ulonglong2 wv = Wt[k * 32 + l];
#pragma unroll
                for (int j = 0; j < 8; j++) {
                    unsigned long long ss = pack2(sx[w][j][k]);
                    ffma2(acc[j][0], ss, wv.x);
                    ffma2(acc[j][1], ss, wv.y);
                }
            }
#pragma unroll
            for (int j = 0; j < 8; j++) {
                int n = base + j;
                if (n >= N) break;
                float4 xv = ((float4*)sx[w][j])[l];
                float n_x = fmaxf(sqrtf(wsum(d4(xv, xv))), MINNORM);          // wsum 1
                float4 mx = unpack4(acc[j][0], acc[j][1]);
                float n_mx = fmaxf(sqrtf(wsum(d4(mx, mx))), MINNORM);         // wsum 2
                float nmv = fminf(tanhf(n_mx / n_x * atanhc(n_x)), MAXN);     // ||mv|| after proj
                float4 mv = f4s(mx, nmv / n_mx);
                float x2 = nmv * nmv;
                float xy = wsum(d4(mv, hb));                                  // wsum 3
                float A = 1.f + 2.f * xy + y2, B = 1.f - x2;
                float den = fmaxf(1.f + 2.f * xy + x2 * y2, MINNORM);
                float invden = 1.f / den;
                float nxh2 = fmaxf(A * A * x2 + 2.f * A * B * xy + B * B * y2, 0.f)
                             * invden * invden;
                float nxh = fmaxf(sqrtf(nxh2), MINNORM);
                float c = (nxh > MAXN) ? (MAXN / nxh) : 1.f;
                float4 xh = f4s(f4axby(A, mv, B, hb), invden * c);
                float nfin = c * nxh;           // ||xh||
                float x2f = nfin * nfin;
                ((float4*)g_xh)[n * 32 + l] = xh;
                if (l == 0) g_x2[n] = x2f;
                float ncl = fmaxf(nfin, MINNORM);
                float4 lx = f4s(xh, atanhc(ncl) / ncl);
                ((float4*)g_lx)[n * 32 + l] = lx;
                float pi = lx.x * at[0]  + lx.y * at[1]  + lx.z * at[2]  + lx.w * at[3];
                float pj = lx.x * at2[0] + lx.y * at2[1] + lx.z * at2[2] + lx.w * at2[3];
#pragma unroll
                for (int o = 4; o; o >>= 1) {
                    pi += __shfl_down_sync(0xffffffffu, pi, o, 8);
                    pj += __shfl_down_sync(0xffffffffu, pj, o, 8);
                }
                if ((l & 7) == 0) { g_hi[n * 4 + h] = pi; g_hj[n * 4 + h] = pj; }
            }
            __syncwarp();
        }
    }
}

// ---------------- fused edge + finalize: warp per destination node ----------------
__global__ __launch_bounds__(256) void fused_edge_kernel(const float* __restrict__ b_e,
                                                         const float* __restrict__ b_h,
                                                         const float* __restrict__ att_hf,
                                                         const float* __restrict__ att_ef,
                                                         float* __restrict__ out, int N) {
    int w = (blockIdx.x * blockDim.x + threadIdx.x) >> 5;
    int l = threadIdx.x & 31;
    if (w >= N) return;
    int dn = w;
    int beg = g_start[dn], end = g_start[dn + 1];

    float4 xd  = ((const float4*)g_xh)[dn * 32 + l];
    float  x2d = g_x2[dn];
    float  ai_l = (l < 4) ? g_ai[dn * 4 + l] : 0.f;
    float  hi_l = (l < 4) ? g_hi[dn * 4 + l] : 0.f;

    // ---- Pass A: distances + euclid logits (4-edge batches) ----
    float sum_d = 0.f;
    float sum_e = 0.f;
    int k = beg;
    for (; k + 4 <= end; k += 4) {
        int s0 = g_csrc[k + 0], s1 = g_csrc[k + 1];
        int s2 = g_csrc[k + 2], s3 = g_csrc[k + 3];
        float4 v0 = ((const float4*)g_xh)[s0 * 32 + l];
        float4 v1 = ((const float4*)g_xh)[s1 * 32 + l];
        float4 v2 = ((const float4*)g_xh)[s2 * 32 + l];
        float4 v3 = ((const float4*)g_xh)[s3 * 32 + l];
        float p0 = d4(xd, v0), p1 = d4(xd, v1), p2 = d4(xd, v2), p3 = d4(xd, v3);
#pragma unroll
        for (int o = 16; o; o >>= 1) {
            p0 += __shfl_xor_sync(0xffffffffu, p0, o);
            p1 += __shfl_xor_sync(0xffffffffu, p1, o);
            p2 += __shfl_xor_sync(0xffffffffu, p2, o);
            p3 += __shfl_xor_sync(0xffffffffu, p3, o);
        }
        if (l < 4) {
            int ssel = (l == 0) ? s0 : (l == 1) ? s1 : (l == 2) ? s2 : s3;
            float pp = (l == 0) ? p0 : (l == 1) ? p1 : (l == 2) ? p2 : p3;
            float yy = g_x2[ssel];
            float A = 1.f - 2.f * pp + yy, B = 1.f - x2d;
            float den = fmaxf(1.f - 2.f * pp + x2d * yy, MINNORM);
            float num2 = fmaxf(A * A * x2d + B * B * yy - 2.f * A * B * pp, 0.f);
            float edd = expf(2.f * atanhc(sqrtf(num2) / den));
            g_de[k + l] = edd;
            sum_d += edd;
            float e0 = expf(lrelu(ai_l + g_aj[s0 * 4 + l]));
            float e1 = expf(lrelu(ai_l + g_aj[s1 * 4 + l]));
            float e2 = expf(lrelu(ai_l + g_aj[s2 * 4 + l]));
            float e3 = expf(lrelu(ai_l + g_aj[s3 * 4 + l]));
            g_le[(k + 0) * 4 + l] = e0;
            g_le[(k + 1) * 4 + l] = e1;
            g_le[(k + 2) * 4 + l] = e2;
            g_le[(k + 3) * 4 + l] = e3;
            sum_e += e0 + e1 + e2 + e3;
        }
    }
    for (; k < end; k++) {
        int s = g_csrc[k];
        float4 xs = ((const float4*)g_xh)[s * 32 + l];
        float xy = wsum(d4(xd, xs));
        float yy = g_x2[s];
        float A = 1.f - 2.f * xy + yy, B = 1.f - x2d;
        float den = fmaxf(1.f - 2.f * xy + x2d * yy, MINNORM);
        float num2 = fmaxf(A * A * x2d + B * B * yy - 2.f * A * B * xy, 0.f);
        float edd = expf(2.f * atanhc(sqrtf(num2) / den));
        if (l == 0) { g_de[k] = edd; sum_d += edd; }
        if (l < 4) {
            float le = expf(lrelu(ai_l + g_aj[s * 4 + l]));
            g_le[k * 4 + l] = le;
            sum_e += le;
        }
    }
    float inv_sd = 1.f / (wsum(sum_d) + 1e-16f);

    // ---- Pass B: hyperbolic logits (lanes 0..3, 4-edge batches) ----
    float sum_h = 0.f;
    k = beg;
    for (; k + 4 <= end; k += 4) {
        if (l < 4) {
            int s0 = g_csrc[k + 0], s1 = g_csrc[k + 1];
            int s2 = g_csrc[k + 2], s3 = g_csrc[k + 3];
            float d0 = g_de[k + 0] * inv_sd, d1 = g_de[k + 1] * inv_sd;
            float d2 = g_de[k + 2] * inv_sd, d3 = g_de[k + 3] * inv_sd;
            float a0 = expf(lrelu((hi_l + g_hj[s0 * 4 + l]) * d0));
            float a1 = expf(lrelu((hi_l + g_hj[s1 * 4 + l]) * d1));
            float a2 = expf(lrelu((hi_l + g_hj[s2 * 4 + l]) * d2));
            float a3 = expf(lrelu((hi_l + g_hj[s3 * 4 + l]) * d3));
            g_ah[(k + 0) * 4 + l] = a0;
            g_ah[(k + 1) * 4 + l] = a1;
            g_ah[(k + 2) * 4 + l] = a2;
            g_ah[(k + 3) * 4 + l] = a3;
            sum_h += a0 + a1 + a2 + a3;
        }
    }
    for (; k < end; k++) {
        if (l < 4) {
            int s = g_csrc[k];
            float dsm = g_de[k] * inv_sd;
            float a = expf(lrelu((hi_l + g_hj[s * 4 + l]) * dsm));
            g_ah[k * 4 + l] = a;
            sum_h += a;
        }
    }

    int h = l >> 3;
    float se = __shfl_sync(0xffffffffu, sum_e, h);
    float sh = __shfl_sync(0xffffffffu, sum_h, h);
    float inv_se = 1.f / (se + 1e-16f);
    float inv_sh = 1.f / (sh + 1e-16f);

    // ---- Pass C: weighted aggregation (4-edge batches for load MLP) ----
    float4 acc_e = make_float4(0.f, 0.f, 0.f, 0.f);
    float4 acc_h = make_float4(0.f, 0.f, 0.f, 0.f);
    k = beg;
    for (; k + 4 <= end; k += 4) {
        int s0 = g_csrc[k], s1 = g_csrc[k + 1], s2 = g_csrc[k + 2], s3 = g_csrc[k + 3];
        float we0 = g_le[(k + 0) * 4 + h] * inv_se;
        float we1 = g_le[(k + 1) * 4 + h] * inv_se;
        float we2 = g_le[(k + 2) * 4 + h] * inv_se;
        float we3 = g_le[(k + 3) * 4 + h] * inv_se;
        float wh0 = g_ah[(k + 0) * 4 + h] * inv_sh;
        float wh1 = g_ah[(k + 1) * 4 + h] * inv_sh;
        float wh2 = g_ah[(k + 2) * 4 + h] * inv_sh;
        float wh3 = g_ah[(k + 3) * 4 + h] * inv_sh;
        float4 xs0 = ((const float4*)g_xe)[s0 * 32 + l];
        float4 xs1 = ((const float4*)g_xe)[s1 * 32 + l];
        float4 xs2 = ((const float4*)g_xe)[s2 * 32 + l];
        float4 xs3 = ((const float4*)g_xe)[s3 * 32 + l];
        float4 ls0 = ((const float4*)g_lx)[s0 * 32 + l];
        float4 ls1 = ((const float4*)g_lx)[s1 * 32 + l];
        float4 ls2 = ((const float4*)g_lx)[s2 * 32 + l];
        float4 ls3 = ((const float4*)g_lx)[s3 * 32 + l];
        acc_e.x = fmaf(we0, xs0.x, fmaf(we1, xs1.x, fmaf(we2, xs2.x, fmaf(we3, xs3.x, acc_e.x))));
        acc_e.y = fmaf(we0, xs0.y, fmaf(we1, xs1.y, fmaf(we2, xs2.y, fmaf(we3, xs3.y, acc_e.y))));
        acc_e.z = fmaf(we0, xs0.z, fmaf(we1, xs1.z, fmaf(we2, xs2.z, fmaf(we3, xs3.z, acc_e.z))));
        acc_e.w = fmaf(we0, xs0.w, fmaf(we1, xs1.w, fmaf(we2, xs2.w, fmaf(we3, xs3.w, acc_e.w))));
        acc_h.x = fmaf(wh0, ls0.x, fmaf(wh1, ls1.x, fmaf(wh2, ls2.x, fmaf(wh3, ls3.x, acc_h.x))));
        acc_h.y = fmaf(wh0, ls0.y, fmaf(wh1, ls1.y, fmaf(wh2, ls2.y, fmaf(wh3, ls3.y, acc_h.y))));
        acc_h.z = fmaf(wh0, ls0.z, fmaf(wh1, ls1.z, fmaf(wh2, ls2.z, fmaf(wh3, ls3.z, acc_h.z))));
        acc_h.w = fmaf(wh0, ls0.w, fmaf(wh1, ls1.w, fmaf(wh2, ls2.w, fmaf(wh3, ls3.w, acc_h.w))));
    }
    for (; k < end; k++) {
        int s = g_csrc[k];
        float we = g_le[k * 4 + h] * inv_se;
        float wh = g_ah[k * 4 + h] * inv_sh;
        float4 xs = ((const float4*)g_xe)[s * 32 + l];
        float4 ls = ((const float4*)g_lx)[s * 32 + l];
        acc_e.x = fmaf(we, xs.x, acc_e.x); acc_e.y = fmaf(we, xs.y, acc_e.y);
        acc_e.z = fmaf(we, xs.z, acc_e.z); acc_e.w = fmaf(we, xs.w, acc_e.w);
        acc_h.x = fmaf(wh, ls.x, acc_h.x); acc_h.y = fmaf(wh, ls.y, acc_h.y);
        acc_h.z = fmaf(wh, ls.z, acc_h.z); acc_h.w = fmaf(wh, ls.w, acc_h.w);
    }

    // ---- Finalize (scalar-norm algebra; only 3 warp reductions) ----
    int n = dn;
    float4 be = ((const float4*)b_e)[l];
    float4 eo = make_float4(fmaxf(acc_e.x + be.x, 0.f), fmaxf(acc_e.y + be.y, 0.f),
                            fmaxf(acc_e.z + be.z, 0.f), fmaxf(acc_e.w + be.w, 0.f));
    float4 bh = ((const float4*)b_h)[l];
    float4 ot = make_float4(fmaxf(acc_h.x + bh.x, 0.f), fmaxf(acc_h.y + bh.y, 0.f),
                            fmaxf(acc_h.z + bh.z, 0.f), fmaxf(acc_h.w + bh.w, 0.f));
    // h_out = proj(expmap0(ot))
    float nt = fmaxf(sqrtf(wsum(d4(ot, ot))), MINNORM);                 // wsum 1
    float nho = fminf(tanhf(nt), MAXN);
    float4 ho = f4s(ot, nho / nt);
    float x2 = nho * nho;
    // ye = proj(expmap0(eo))
    float ne2 = wsum(d4(eo, eo));                                       // wsum 2
    float ne = fmaxf(sqrtf(ne2), MINNORM);
    float nye = fminf(tanhf(ne), MAXN);
    float4 ye = f4s(eo, nye / ne);
    float y2 = nye * nye;
    // dist_f = pdist(ho, ye) * att_hf
    float xy = wsum(d4(ho, ye));                                        // wsum 3
    float A = 1.f - 2.f * xy + y2, B = 1.f - x2;
    float den = fmaxf(1.f - 2.f * xy + x2 * y2, MINNORM);
    float num2 = fmaxf(A * A * x2 + B * B * y2 - 2.f * A * B * xy, 0.f);
    float r = 2.f * atanhc(sqrtf(num2) / den) * att_hf[0];
    // xe2 = proj(mobius_scalar_mul(r, ye)); xe2 parallel to ye
    float ny = fmaxf(nye, MINNORM);
    float t3 = tanhf(r * atanhc(ny));
    float kxe = t3 / ny;
    float nxe2 = fabsf(kxe) * nye;
    float c2 = (nxe2 > MAXN) ? (MAXN / fmaxf(nxe2, MINNORM)) : 1.f;
    float kxe2 = kxe * c2;
    float4 xe2 = f4s(ye, kxe2);
    float nxe2c = nxe2 * c2;
    float y2b = nxe2c * nxe2c;
    float xyb = xy * kxe2;
    // h_fused = proj(mobius_add(ho, xe2))
    float A2 = 1.f + 2.f * xyb + y2b, B2 = 1.f - x2;
    float den2 = fmaxf(1.f + 2.f * xyb + x2 * y2b, MINNORM);
    float invden2 = 1.f / den2;
    float nhf2 = fmaxf(A2 * A2 * x2 + 2.f * A2 * B2 * xyb + B2 * B2 * y2b, 0.f)
                 * invden2 * invden2;
    float nhf = fmaxf(sqrtf(nhf2), MINNORM);
    float c3 = (nhf > MAXN) ? (MAXN / nhf) : 1.f;
    float4 hf = f4s(f4axby(A2, ho, B2, xe2), invden2 * c3);
    // e_fused = eo + de * lh;  lh = logmap0(ho)
    float nclh = fmaxf(nho, MINNORM);
    float alh = atanhc(nclh);
    float kl = alh / nclh;
    float4 lh = f4s(ho, kl);
    float dot_ho_eo = xy * ne / nye;   // <ho, eo> from <ho, ye>
    float de = (alh * alh - 2.f * kl * dot_ho_eo + ne2) * att_ef[0];
    float4 ef = make_float4(eo.x + de * lh.x, eo.y + de * lh.y,
                            eo.z + de * lh.z, eo.w + de * lh.w);
    ((float4*)out)[n * 32 + l] = hf;
    ((float4*)out)[(size_t)N * 32 + n * 32 + l] = ef;
}

// ---------------- launch ----------------
extern "C" void kernel_launch(void* const* d_in, const int* in_sizes, int n_in,
                              void* d_out, int out_size) {
    const float* x_e      = (const float*)d_in[0];
    const float* x_h      = (const float*)d_in[1];
    const int*   ei       = (const int*)d_in[2];
    const float* W_e      = (const float*)d_in[3];
    const float* b_lin_e  = (const float*)d_in[4];
    const float* att_e    = (const float*)d_in[5];
    const float* b_e      = (const float*)d_in[6];
    const float* W_h      = (const float*)d_in[7];
    const float* b_lin_h  = (const float*)d_in[8];
    const float* att_h    = (const float*)d_in[9];
    const float* b_h      = (const float*)d_in[10];
    const float* att_hf   = (const float*)d_in[11];
    const float* att_ef   = (const float*)d_in[12];
    float* out = (float*)d_out;

    int N  = in_sizes[0] / D_;
    int E  = in_sizes[2] / 2;
    int EP = E + N;
    int ngrp = (N + 31) / 32;
    int ngrid = (ngrp + 1) / 2;          // 2 groups per block -> single resident wave
    int nsb = (N + 255) / 256;           // scan blocks (<=256)

    zero_kernel<<<(N + 255) / 256, 256>>>(N);
    transpose_kernel<<<(2 * D_ * D_ + 255) / 256, 256>>>(W_e, W_h);
    count_kernel<<<(EP + 255) / 256, 256>>>(ei, E, EP);
    node_e_kernel<<<ngrid, 128>>>(x_e, b_lin_e, att_e, N, ngrp);
    node_h_kernel<<<ngrid, 128>>>(x_h, b_lin_h, att_h, N, ngrp);
    scan1_kernel<<<nsb, 256>>>(N);
    scan2_kernel<<<1, 256>>>(nsb);
    scan3_kernel<<<(N + 255) / 256, 256>>>(N, EP);
    scatter_kernel<<<(EP + 255) / 256, 256>>>(ei, E, EP);
    fused_edge_kernel<<<(N * 32 + 255) / 256, 256>>>(b_e, b_h, att_hf, att_ef, out, N);
}

// round 5
// speedup vs baseline: 2.5411x; 1.0297x over previous
#include <cuda_runtime.h>
#include <math.h>

#define D_ 128
#define NMAX 50016
#define EPMAX 550032
#define MAXN 0.99999f
#define MINNORM 1e-15f

// ---------------- scratch ----------------
__device__ float g_xe[NMAX * D_];
__device__ float g_xh[NMAX * D_];
__device__ float g_lx[NMAX * D_];
__device__ float g_ai[NMAX * 4];
__device__ float g_aj[NMAX * 4];
__device__ float g_hi[NMAX * 4];
__device__ float g_hj[NMAX * 4];
__device__ float g_x2[NMAX];
__device__ float g_de[EPMAX];       // exp(distance)
__device__ float g_WtE[D_ * D_];
__device__ float g_WtH[D_ * D_];
__device__ int   g_deg[NMAX];
__device__ int   g_cur[NMAX];
__device__ int   g_start[NMAX + 1];
__device__ int   g_csrc[EPMAX];
__device__ int   g_bsum[256];

// ---------------- helpers ----------------
__device__ __forceinline__ float atanhc(float x) {
    x = fminf(fmaxf(x, -1.0f + 1e-7f), 1.0f - 1e-7f);
    return atanhf(x);
}
__device__ __forceinline__ float wsum(float v) {
#pragma unroll
    for (int o = 16; o; o >>= 1) v += __shfl_xor_sync(0xffffffffu, v, o);
    return v;
}
__device__ __forceinline__ float d4(float4 a, float4 b) {
    return a.x * b.x + a.y * b.y + a.z * b.z + a.w * b.w;
}
__device__ __forceinline__ float4 f4s(float4 a, float s) {
    return make_float4(a.x * s, a.y * s, a.z * s, a.w * s);
}
__device__ __forceinline__ float4 f4axby(float a, float4 x, float b, float4 y) {
    return make_float4(a * x.x + b * y.x, a * x.y + b * y.y,
                       a * x.z + b * y.z, a * x.w + b * y.w);
}
__device__ __forceinline__ float lrelu(float v) { return v >= 0.f ? v : 0.2f * v; }

// packed f32x2 helpers (Blackwell FFMA2)
__device__ __forceinline__ void ffma2(unsigned long long &acc,
                                      unsigned long long a, unsigned long long b) {
    asm("fma.rn.f32x2 %0, %1, %2, %3;" : "=l"(acc) : "l"(a), "l"(b), "l"(acc));
}
__device__ __forceinline__ unsigned long long pack2(float s) {
    unsigned u = __float_as_uint(s);
    unsigned long long r;
    asm("mov.b64 %0, {%1, %1};" : "=l"(r) : "r"(u));
    return r;
}
__device__ __forceinline__ float4 unpack4(unsigned long long lo, unsigned long long hi) {
    float4 v;
    asm("mov.b64 {%0, %1}, %2;" : "=f"(v.x), "=f"(v.y) : "l"(lo));
    asm("mov.b64 {%0, %1}, %2;" : "=f"(v.z), "=f"(v.w) : "l"(hi));
    return v;
}

// ---------------- init: zero degrees + transpose weights ----------------
__global__ __launch_bounds__(256) void init_kernel(const float* __restrict__ We,
                                                   const float* __restrict__ Wh, int N) {
    int i = blockIdx.x * blockDim.x + threadIdx.x;
    if (i < N) g_deg[i] = 0;
    if (i < 2 * D_ * D_) {
        int m = i >> 14;
        int k = (i >> 7) & 127;
        int c = i & 127;
        if (m == 0) g_WtE[k * D_ + c] = We[c * D_ + k];
        else        g_WtH[k * D_ + c] = Wh[c * D_ + k];
    }
}

__global__ __launch_bounds__(256) void count_kernel(const int* __restrict__ ei, int E, int EP) {
    int e = blockIdx.x * blockDim.x + threadIdx.x;
    if (e >= EP) return;
    int dn = (e < E) ? ei[E + e] : (e - E);
    atomicAdd(&g_deg[dn], 1);
}

__global__ __launch_bounds__(256) void scan1_kernel(int N) {
    __shared__ int sm[256];
    int i = blockIdx.x * 256 + threadIdx.x;
    int v = (i < N) ? g_deg[i] : 0;
    sm[threadIdx.x] = v;
    __syncthreads();
#pragma unroll
    for (int d = 1; d < 256; d <<= 1) {
        int t = (threadIdx.x >= d) ? sm[threadIdx.x - d] : 0;
        __syncthreads();
        sm[threadIdx.x] += t;
        __syncthreads();
    }
    if (i < N) g_start[i] = sm[threadIdx.x] - v;
    if (threadIdx.x == 255) g_bsum[blockIdx.x] = sm[255];
}

__global__ __launch_bounds__(256) void scan2_kernel(int nb) {
    __shared__ int sm[256];
    int v = (threadIdx.x < nb) ? g_bsum[threadIdx.x] : 0;
    sm[threadIdx.x] = v;
    __syncthreads();
#pragma unroll
    for (int d = 1; d < 256; d <<= 1) {
        int t = (threadIdx.x >= d) ? sm[threadIdx.x - d] : 0;
        __syncthreads();
        sm[threadIdx.x] += t;
        __syncthreads();
    }
    g_bsum[threadIdx.x] = sm[threadIdx.x] - v;
}

__global__ __launch_bounds__(256) void scan3_kernel(int N, int EP) {
    int i = blockIdx.x * 256 + threadIdx.x;
    if (i < N) { g_start[i] += g_bsum[i >> 8]; g_cur[i] = 0; }
    if (i == 0) g_start[N] = EP;
}

__global__ __launch_bounds__(256) void scatter_kernel(const int* __restrict__ ei, int E, int EP) {
    int e = blockIdx.x * blockDim.x + threadIdx.x;
    if (e >= EP) return;
    int s, dn;
    if (e < E) { s = ei[e]; dn = ei[E + e]; } else { s = dn = e - E; }
    int pos = atomicAdd(&g_cur[dn], 1);
    g_csrc[g_start[dn] + pos] = s;
}

// ---------------- node kernels: 8 nodes/warp, packed-dup smem + FFMA2 ----------------
__global__ __launch_bounds__(128) void node_e_kernel(const float* __restrict__ x,
                                                     const float* __restrict__ b_lin,
                                                     const float* __restrict__ att,
                                                     int N) {
    __shared__ __align__(16) unsigned long long sxx[4][8][D_];
    int w = threadIdx.x >> 5, l = threadIdx.x & 31;
    int base = blockIdx.x * 32 + w * 8;
    if (base >= N) return;
#pragma unroll
    for (int j = 0; j < 8; j++) {
        int n = min(base + j, N - 1);
        float4 xv = ((const float4*)x)[n * 32 + l];
        sxx[w][j][4 * l + 0] = pack2(xv.x);
        sxx[w][j][4 * l + 1] = pack2(xv.y);
        sxx[w][j][4 * l + 2] = pack2(xv.z);
        sxx[w][j][4 * l + 3] = pack2(xv.w);
    }
    __syncwarp();
    unsigned long long acc[8][2];
#pragma unroll
    for (int j = 0; j < 8; j++) { acc[j][0] = 0ull; acc[j][1] = 0ull; }
    const ulonglong2* Wt = (const ulonglong2*)g_WtE;
#pragma unroll 4
    for (int k = 0; k < D_; k += 2) {
        ulonglong2 wv0 = Wt[k * 32 + l];
        ulonglong2 wv1 = Wt[(k + 1) * 32 + l];
#pragma unroll
        for (int j = 0; j < 8; j++) {
            ulonglong2 pp = *(const ulonglong2*)&sxx[w][j][k];
            ffma2(acc[j][0], pp.x, wv0.x);
            ffma2(acc[j][1], pp.x, wv0.y);
            ffma2(acc[j][0], pp.y, wv1.x);
            ffma2(acc[j][1], pp.y, wv1.y);
        }
    }
    float4 bv = ((const float4*)b_lin)[l];
    int h = l >> 3, j0 = (l & 7) * 4;
    const float* at  = att + h * 64 + j0;
    const float* at2 = at + 32;
#pragma unroll
    for (int j = 0; j < 8; j++) {
        int n = base + j;
        if (n >= N) break;
        float4 a = unpack4(acc[j][0], acc[j][1]);
        a.x += bv.x; a.y += bv.y; a.z += bv.z; a.w += bv.w;
        ((float4*)g_xe)[n * 32 + l] = a;
        float pi = a.x * at[0]  + a.y * at[1]  + a.z * at[2]  + a.w * at[3];
        float pj = a.x * at2[0] + a.y * at2[1] + a.z * at2[2] + a.w * at2[3];
#pragma unroll
        for (int o = 4; o; o >>= 1) {
            pi += __shfl_down_sync(0xffffffffu, pi, o, 8);
            pj += __shfl_down_sync(0xffffffffu, pj, o, 8);
        }
        if ((l & 7) == 0) { g_ai[n * 4 + h] = pi; g_aj[n * 4 + h] = pj; }
    }
}

__global__ __launch_bounds__(128) void node_h_kernel(const float* __restrict__ x,
                                                     const float* __restrict__ b_lin,
                                                     const float* __restrict__ att,
                                                     int N) {
    __shared__ __align__(16) unsigned long long sxx[4][8][D_];
    int w = threadIdx.x >> 5, l = threadIdx.x & 31;
    int base = blockIdx.x * 32 + w * 8;
    if (base >= N) return;
    float nx[8];
#pragma unroll
    for (int j = 0; j < 8; j++) {
        int n = min(base + j, N - 1);
        float4 xv = ((const float4*)x)[n * 32 + l];
        nx[j] = fmaxf(sqrtf(wsum(d4(xv, xv))), MINNORM);
        sxx[w][j][4 * l + 0] = pack2(xv.x);
        sxx[w][j][4 * l + 1] = pack2(xv.y);
        sxx[w][j][4 * l + 2] = pack2(xv.z);
        sxx[w][j][4 * l + 3] = pack2(xv.w);
    }
    __syncwarp();
    unsigned long long acc[8][2];
#pragma unroll
    for (int j = 0; j < 8; j++) { acc[j][0] = 0ull; acc[j][1] = 0ull; }
    const ulonglong2* Wt = (const ulonglong2*)g_WtH;
#pragma unroll 4
    for (int k = 0; k < D_; k += 2) {
        ulonglong2 wv0 = Wt[k * 32 + l];
        ulonglong2 wv1 = Wt[(k + 1) * 32 + l];
#pragma unroll
        for (int j = 0; j < 8; j++) {
            ulonglong2 pp = *(const ulonglong2*)&sxx[w][j][k];
            ffma2(acc[j][0], pp.x, wv0.x);
            ffma2(acc[j][1], pp.x, wv0.y);
            ffma2(acc[j][0], pp.y, wv1.x);
            ffma2(acc[j][1], pp.y, wv1.y);
        }
    }
    // hoisted bias point hb = proj(expmap0(b_lin_h)); scalar norms
    float4 bvv = ((const float4*)b_lin)[l];
    float nb = fmaxf(sqrtf(wsum(d4(bvv, bvv))), MINNORM);
    float nhb = fminf(tanhf(nb), MAXN);
    float4 hb = f4s(bvv, nhb / nb);
    float y2 = nhb * nhb;

    int h = l >> 3, j0 = (l & 7) * 4;
    const float* at  = att + h * 64 + j0;
    const float* at2 = at + 32;
#pragma unroll
    for (int j = 0; j < 8; j++) {
        int n = base + j;
        if (n >= N) break;
        float n_x = nx[j];
        float4 mx = unpack4(acc[j][0], acc[j][1]);
        float n_mx = fmaxf(sqrtf(wsum(d4(mx, mx))), MINNORM);
        float nmv = fminf(tanhf(n_mx / n_x * atanhc(n_x)), MAXN);
        float4 mv = f4s(mx, nmv / n_mx);
        float x2 = nmv * nmv;
        float xy = wsum(d4(mv, hb));
        float A = 1.f + 2.f * xy + y2, B = 1.f - x2;
        float den = fmaxf(1.f + 2.f * xy + x2 * y2, MINNORM);
        float invden = 1.f / den;
        float nxh2 = fmaxf(A * A * x2 + 2.f * A * B * xy + B * B * y2, 0.f)
                     * invden * invden;
        float nxh = fmaxf(sqrtf(nxh2), MINNORM);
        float c = (nxh > MAXN) ? (MAXN / nxh) : 1.f;
        float4 xh = f4s(f4axby(A, mv, B, hb), invden * c);
        float nfin = c * nxh;
        float x2f = nfin * nfin;
        ((float4*)g_xh)[n * 32 + l] = xh;
        if (l == 0) g_x2[n] = x2f;
        float ncl = fmaxf(nfin, MINNORM);
        float4 lx = f4s(xh, atanhc(ncl) / ncl);
        ((float4*)g_lx)[n * 32 + l] = lx;
        float pi = lx.x * at[0]  + lx.y * at[1]  + lx.z * at[2]  + lx.w * at[3];
        float pj = lx.x * at2[0] + lx.y * at2[1] + lx.z * at2[2] + lx.w * at2[3];
#pragma unroll
        for (int o = 4; o; o >>= 1) {
            pi += __shfl_down_sync(0xffffffffu, pi, o, 8);
            pj += __shfl_down_sync(0xffffffffu, pj, o, 8);
        }
        if ((l & 7) == 0) { g_hi[n * 4 + h] = pi; g_hj[n * 4 + h] = pj; }
    }
}

// ---------------- fused edge (2 passes, unnormalized aggregation) + finalize ----------------
__global__ __launch_bounds__(256) void fused_edge_kernel(const float* __restrict__ b_e,
                                                         const float* __restrict__ b_h,
                                                         const float* __restrict__ att_hf,
                                                         const float* __restrict__ att_ef,
                                                         float* __restrict__ out, int N) {
    int w = (blockIdx.x * blockDim.x + threadIdx.x) >> 5;
    int l = threadIdx.x & 31;
    if (w >= N) return;
    int dn = w;
    int beg = g_start[dn], end = g_start[dn + 1];
    int h = l >> 3;
    bool leader = (l & 7) == 0;

    float4 xd  = ((const float4*)g_xh)[dn * 32 + l];
    float  x2d = g_x2[dn];
    float  ai_l = g_ai[dn * 4 + h];
    float  hi_l = g_hi[dn * 4 + h];

    // ---- Pass A: distances + euclid softmax-weighted aggregation (unnormalized) ----
    float sum_d = 0.f, sum_e = 0.f;
    float4 acc_e = make_float4(0.f, 0.f, 0.f, 0.f);
    int k = beg;
    for (; k + 4 <= end; k += 4) {
        int s0 = g_csrc[k + 0], s1 = g_csrc[k + 1];
        int s2 = g_csrc[k + 2], s3 = g_csrc[k + 3];
        float4 v0 = ((const float4*)g_xh)[s0 * 32 + l];
        float4 v1 = ((const float4*)g_xh)[s1 * 32 + l];
        float4 v2 = ((const float4*)g_xh)[s2 * 32 + l];
        float4 v3 = ((const float4*)g_xh)[s3 * 32 + l];
        float4 e0 = ((const float4*)g_xe)[s0 * 32 + l];
        float4 e1 = ((const float4*)g_xe)[s1 * 32 + l];
        float4 e2 = ((const float4*)g_xe)[s2 * 32 + l];
        float4 e3 = ((const float4*)g_xe)[s3 * 32 + l];
        float le0 = expf(lrelu(ai_l + g_aj[s0 * 4 + h]));
        float le1 = expf(lrelu(ai_l + g_aj[s1 * 4 + h]));
        float le2 = expf(lrelu(ai_l + g_aj[s2 * 4 + h]));
        float le3 = expf(lrelu(ai_l + g_aj[s3 * 4 + h]));
        acc_e.x = fmaf(le0, e0.x, fmaf(le1, e1.x, fmaf(le2, e2.x, fmaf(le3, e3.x, acc_e.x))));
        acc_e.y = fmaf(le0, e0.y, fmaf(le1, e1.y, fmaf(le2, e2.y, fmaf(le3, e3.y, acc_e.y))));
        acc_e.z = fmaf(le0, e0.z, fmaf(le1, e1.z, fmaf(le2, e2.z, fmaf(le3, e3.z, acc_e.z))));
        acc_e.w = fmaf(le0, e0.w, fmaf(le1, e1.w, fmaf(le2, e2.w, fmaf(le3, e3.w, acc_e.w))));
        if (leader) sum_e += le0 + le1 + le2 + le3;
        float p0 = d4(xd, v0), p1 = d4(xd, v1), p2 = d4(xd, v2), p3 = d4(xd, v3);
#pragma unroll
        for (int o = 16; o; o >>= 1) {
            p0 += __shfl_xor_sync(0xffffffffu, p0, o);
            p1 += __shfl_xor_sync(0xffffffffu, p1, o);
            p2 += __shfl_xor_sync(0xffffffffu, p2, o);
            p3 += __shfl_xor_sync(0xffffffffu, p3, o);
        }
        if (l < 4) {
            int ssel = (l == 0) ? s0 : (l == 1) ? s1 : (l == 2) ? s2 : s3;
            float pp = (l == 0) ? p0 : (l == 1) ? p1 : (l == 2) ? p2 : p3;
            float yy = g_x2[ssel];
            float A = 1.f - 2.f * pp + yy, B = 1.f - x2d;
            float den = fmaxf(1.f - 2.f * pp + x2d * yy, MINNORM);
            float num2 = fmaxf(A * A * x2d + B * B * yy - 2.f * A * B * pp, 0.f);
            float edd = expf(2.f * atanhc(sqrtf(num2) / den));
            g_de[k + l] = edd;
            sum_d += edd;
        }
    }
    for (; k < end; k++) {
        int s = g_csrc[k];
        float4 xs = ((const float4*)g_xh)[s * 32 + l];
        float4 es = ((const float4*)g_xe)[s * 32 + l];
        float le = expf(lrelu(ai_l + g_aj[s * 4 + h]));
        acc_e.x = fmaf(le, es.x, acc_e.x); acc_e.y = fmaf(le, es.y, acc_e.y);
        acc_e.z = fmaf(le, es.z, acc_e.z); acc_e.w = fmaf(le, es.w, acc_e.w);
        if (leader) sum_e += le;
        float xy = wsum(d4(xd, xs));
        float yy = g_x2[s];
        float A = 1.f - 2.f * xy + yy, B = 1.f - x2d;
        float den = fmaxf(1.f - 2.f * xy + x2d * yy, MINNORM);
        float num2 = fmaxf(A * A * x2d + B * B * yy - 2.f * A * B * xy, 0.f);
        float edd = expf(2.f * atanhc(sqrtf(num2) / den));
        if (l == 0) { g_de[k] = edd; sum_d += edd; }
    }
    float inv_sd = 1.f / (wsum(sum_d) + 1e-16f);

    // ---- Pass B: hyperbolic softmax-weighted aggregation (unnormalized) ----
    float sum_h = 0.f;
    float4 acc_h = make_float4(0.f, 0.f, 0.f, 0.f);
    k = beg;
    for (; k + 4 <= end; k += 4) {
        int s0 = g_csrc[k + 0], s1 = g_csrc[k + 1];
        int s2 = g_csrc[k + 2], s3 = g_csrc[k + 3];
        float4 l0 = ((const float4*)g_lx)[s0 * 32 + l];
        float4 l1 = ((const float4*)g_lx)[s1 * 32 + l];
        float4 l2 = ((const float4*)g_lx)[s2 * 32 + l];
        float4 l3 = ((const float4*)g_lx)[s3 * 32 + l];
        float d0 = g_de[k + 0] * inv_sd, d1 = g_de[k + 1] * inv_sd;
        float d2 = g_de[k + 2] * inv_sd, d3 = g_de[k + 3] * inv_sd;
        float a0 = expf(lrelu((hi_l + g_hj[s0 * 4 + h]) * d0));
        float a1 = expf(lrelu((hi_l + g_hj[s1 * 4 + h]) * d1));
        float a2 = expf(lrelu((hi_l + g_hj[s2 * 4 + h]) * d2));
        float a3 = expf(lrelu((hi_l + g_hj[s3 * 4 + h]) * d3));
        acc_h.x = fmaf(a0, l0.x, fmaf(a1, l1.x, fmaf(a2, l2.x, fmaf(a3, l3.x, acc_h.x))));
        acc_h.y = fmaf(a0, l0.y, fmaf(a1, l1.y, fmaf(a2, l2.y, fmaf(a3, l3.y, acc_h.y))));
        acc_h.z = fmaf(a0, l0.z, fmaf(a1, l1.z, fmaf(a2, l2.z, fmaf(a3, l3.z, acc_h.z))));
        acc_h.w = fmaf(a0, l0.w, fmaf(a1, l1.w, fmaf(a2, l2.w, fmaf(a3, l3.w, acc_h.w))));
        if (leader) sum_h += a0 + a1 + a2 + a3;
    }
    for (; k < end; k++) {
        int s = g_csrc[k];
        float4 ls = ((const float4*)g_lx)[s * 32 + l];
        float dsm = g_de[k] * inv_sd;
        float a = expf(lrelu((hi_l + g_hj[s * 4 + h]) * dsm));
        acc_h.x = fmaf(a, ls.x, acc_h.x); acc_h.y = fmaf(a, ls.y, acc_h.y);
        acc_h.z = fmaf(a, ls.z, acc_h.z); acc_h.w = fmaf(a, ls.w, acc_h.w);
        if (leader) sum_h += a;
    }

    // broadcast per-head sums from head-leader lanes
    float se = __shfl_sync(0xffffffffu, sum_e, h << 3);
    float sh = __shfl_sync(0xffffffffu, sum_h, h << 3);
    float inv_se = 1.f / (se + 1e-16f);
    float inv_sh = 1.f / (sh + 1e-16f);

    // ---- Finalize (scalar-norm algebra; 3 warp reductions) ----
    int n = dn;
    float4 be = ((const float4*)b_e)[l];
    float4 eo = make_float4(fmaxf(fmaf(acc_e.x, inv_se, be.x), 0.f),
                            fmaxf(fmaf(acc_e.y, inv_se, be.y), 0.f),
                            fmaxf(fmaf(acc_e.z, inv_se, be.z), 0.f),
                            fmaxf(fmaf(acc_e.w, inv_se, be.w), 0.f));
    float4 bh = ((const float4*)b_h)[l];
    float4 ot = make_float4(fmaxf(fmaf(acc_h.x, inv_sh, bh.x), 0.f),
                            fmaxf(fmaf(acc_h.y, inv_sh, bh.y), 0.f),
                            fmaxf(fmaf(acc_h.z, inv_sh, bh.z), 0.f),
                            fmaxf(fmaf(acc_h.w, inv_sh, bh.w), 0.f));
    float nt = fmaxf(sqrtf(wsum(d4(ot, ot))), MINNORM);
    float nho = fminf(tanhf(nt), MAXN);
    float4 ho = f4s(ot, nho / nt);
    float x2 = nho * nho;
    float ne2 = wsum(d4(eo, eo));
    float ne = fmaxf(sqrtf(ne2), MINNORM);
    float nye = fminf(tanhf(ne), MAXN);
    float4 ye = f4s(eo, nye / ne);
    float y2 = nye * nye;
    float xy = wsum(d4(ho, ye));
    float A = 1.f - 2.f * xy + y2, B = 1.f - x2;
    float den = fmaxf(1.f - 2.f * xy + x2 * y2, MINNORM);
    float num2 = fmaxf(A * A * x2 + B * B * y2 - 2.f * A * B * xy, 0.f);
    float r = 2.f * atanhc(sqrtf(num2) / den) * att_hf[0];
    float ny = fmaxf(nye, MINNORM);
    float t3 = tanhf(r * atanhc(ny));
    float kxe = t3 / ny;
    float nxe2 = fabsf(kxe) * nye;
    float c2 = (nxe2 > MAXN) ? (MAXN / fmaxf(nxe2, MINNORM)) : 1.f;
    float kxe2 = kxe * c2;
    float4 xe2 = f4s(ye, kxe2);
    float nxe2c = nxe2 * c2;
    float y2b = nxe2c * nxe2c;
    float xyb = xy * kxe2;
    float A2 = 1.f + 2.f * xyb + y2b, B2 = 1.f - x2;
    float den2 = fmaxf(1.f + 2.f * xyb + x2 * y2b, MINNORM);
    float invden2 = 1.f / den2;
    float nhf2 = fmaxf(A2 * A2 * x2 + 2.f * A2 * B2 * xyb + B2 * B2 * y2b, 0.f)
                 * invden2 * invden2;
    float nhf = fmaxf(sqrtf(nhf2), MINNORM);
    float c3 = (nhf > MAXN) ? (MAXN / nhf) : 1.f;
    float4 hf = f4s(f4axby(A2, ho, B2, xe2), invden2 * c3);
    float nclh = fmaxf(nho, MINNORM);
    float alh = atanhc(nclh);
    float kl = alh / nclh;
    float4 lh = f4s(ho, kl);
    float dot_ho_eo = xy * ne / nye;
    float de = (alh * alh - 2.f * kl * dot_ho_eo + ne2) * att_ef[0];
    float4 ef = make_float4(eo.x + de * lh.x, eo.y + de * lh.y,
                            eo.z + de * lh.z, eo.w + de * lh.w);
    ((float4*)out)[n * 32 + l] = hf;
    ((float4*)out)[(size_t)N * 32 + n * 32 + l] = ef;
}

// ---------------- launch ----------------
extern "C" void kernel_launch(void* const* d_in, const int* in_sizes, int n_in,
                              void* d_out, int out_size) {
    const float* x_e      = (const float*)d_in[0];
    const float* x_h      = (const float*)d_in[1];
    const int*   ei       = (const int*)d_in[2];
    const float* W_e      = (const float*)d_in[3];
    const float* b_lin_e  = (const float*)d_in[4];
    const float* att_e    = (const float*)d_in[5];
    const float* b_e      = (const float*)d_in[6];
    const float* W_h      = (const float*)d_in[7];
    const float* b_lin_h  = (const float*)d_in[8];
    const float* att_h    = (const float*)d_in[9];
    const float* b_h      = (const float*)d_in[10];
    const float* att_hf   = (const float*)d_in[11];
    const float* att_ef   = (const float*)d_in[12];
    float* out = (float*)d_out;

    int N  = in_sizes[0] / D_;
    int E  = in_sizes[2] / 2;
    int EP = E + N;
    int nsb = (N + 255) / 256;
    int ninit = (N > 2 * D_ * D_) ? N : 2 * D_ * D_;

    init_kernel<<<(ninit + 255) / 256, 256>>>(W_e, W_h, N);
    count_kernel<<<(EP + 255) / 256, 256>>>(ei, E, EP);
    node_e_kernel<<<(N + 31) / 32, 128>>>(x_e, b_lin_e, att_e, N);
    node_h_kernel<<<(N + 31) / 32, 128>>>(x_h, b_lin_h, att_h, N);
    scan1_kernel<<<nsb, 256>>>(N);
    scan2_kernel<<<1, 256>>>(nsb);
    scan3_kernel<<<(N + 255) / 256, 256>>>(N, EP);
    scatter_kernel<<<(EP + 255) / 256, 256>>>(ei, E, EP);
    fused_edge_kernel<<<(N * 32 + 255) / 256, 256>>>(b_e, b_h, att_hf, att_ef, out, N);
}

// round 6
// speedup vs baseline: 2.7846x; 1.0958x over previous
#include <cuda_runtime.h>
#include <math.h>

#define D_ 128
#define NMAX 50016
#define EPMAX 550032
#define MAXN 0.99999f
#define MINNORM 1e-15f

// ---------------- scratch ----------------
__device__ float g_xe[NMAX * D_];
__device__ float g_xh[NMAX * D_];
__device__ float g_lx[NMAX * D_];
__device__ float g_ai[NMAX * 4];
__device__ float g_aj[NMAX * 4];
__device__ float g_hi[NMAX * 4];
__device__ float g_hj[NMAX * 4];
__device__ float g_x2[NMAX];
__device__ float g_de[EPMAX];       // exp(distance)
__device__ float g_WtE[D_ * D_];
__device__ float g_WtH[D_ * D_];
__device__ int   g_deg[NMAX];
__device__ int   g_cur[NMAX];
__device__ int   g_start[NMAX + 1];
__device__ int   g_csrc[EPMAX];
__device__ int   g_bsum[256];

// ---------------- helpers ----------------
__device__ __forceinline__ float atanhc(float x) {
    x = fminf(fmaxf(x, -1.0f + 1e-7f), 1.0f - 1e-7f);
    return atanhf(x);
}
__device__ __forceinline__ float wsum(float v) {
#pragma unroll
    for (int o = 16; o; o >>= 1) v += __shfl_xor_sync(0xffffffffu, v, o);
    return v;
}
__device__ __forceinline__ float d4(float4 a, float4 b) {
    return a.x * b.x + a.y * b.y + a.z * b.z + a.w * b.w;
}
__device__ __forceinline__ float4 f4s(float4 a, float s) {
    return make_float4(a.x * s, a.y * s, a.z * s, a.w * s);
}
__device__ __forceinline__ float4 f4axby(float a, float4 x, float b, float4 y) {
    return make_float4(a * x.x + b * y.x, a * x.y + b * y.y,
                       a * x.z + b * y.z, a * x.w + b * y.w);
}
__device__ __forceinline__ float lrelu(float v) { return v >= 0.f ? v : 0.2f * v; }

// packed f32x2 helpers (Blackwell FFMA2)
__device__ __forceinline__ void ffma2(unsigned long long &acc,
                                      unsigned long long a, unsigned long long b) {
    asm("fma.rn.f32x2 %0, %1, %2, %3;" : "=l"(acc) : "l"(a), "l"(b), "l"(acc));
}
__device__ __forceinline__ unsigned long long pack2(float s) {
    unsigned u = __float_as_uint(s);
    unsigned long long r;
    asm("mov.b64 %0, {%1, %1};" : "=l"(r) : "r"(u));
    return r;
}
__device__ __forceinline__ float4 unpack4(unsigned long long lo, unsigned long long hi) {
    float4 v;
    asm("mov.b64 {%0, %1}, %2;" : "=f"(v.x), "=f"(v.y) : "l"(lo));
    asm("mov.b64 {%0, %1}, %2;" : "=f"(v.z), "=f"(v.w) : "l"(hi));
    return v;
}

// ---------------- init: zero degrees + transpose weights ----------------
__global__ __launch_bounds__(256) void init_kernel(const float* __restrict__ We,
                                                   const float* __restrict__ Wh, int N) {
    int i = blockIdx.x * blockDim.x + threadIdx.x;
    if (i < N) g_deg[i] = 0;
    if (i < 2 * D_ * D_) {
        int m = i >> 14;
        int k = (i >> 7) & 127;
        int c = i & 127;
        if (m == 0) g_WtE[k * D_ + c] = We[c * D_ + k];
        else        g_WtH[k * D_ + c] = Wh[c * D_ + k];
    }
}

__global__ __launch_bounds__(256) void count_kernel(const int* __restrict__ ei, int E, int EP) {
    int e = blockIdx.x * blockDim.x + threadIdx.x;
    if (e >= EP) return;
    int dn = (e < E) ? ei[E + e] : (e - E);
    atomicAdd(&g_deg[dn], 1);
}

__global__ __launch_bounds__(256) void scan1_kernel(int N) {
    __shared__ int sm[256];
    int i = blockIdx.x * 256 + threadIdx.x;
    int v = (i < N) ? g_deg[i] : 0;
    sm[threadIdx.x] = v;
    __syncthreads();
#pragma unroll
    for (int d = 1; d < 256; d <<= 1) {
        int t = (threadIdx.x >= d) ? sm[threadIdx.x - d] : 0;
        __syncthreads();
        sm[threadIdx.x] += t;
        __syncthreads();
    }
    if (i < N) g_start[i] = sm[threadIdx.x] - v;
    if (threadIdx.x == 255) g_bsum[blockIdx.x] = sm[255];
}

__global__ __launch_bounds__(256) void scan2_kernel(int nb) {
    __shared__ int sm[256];
    int v = (threadIdx.x < nb) ? g_bsum[threadIdx.x] : 0;
    sm[threadIdx.x] = v;
    __syncthreads();
#pragma unroll
    for (int d = 1; d < 256; d <<= 1) {
        int t = (threadIdx.x >= d) ? sm[threadIdx.x - d] : 0;
        __syncthreads();
        sm[threadIdx.x] += t;
        __syncthreads();
    }
    g_bsum[threadIdx.x] = sm[threadIdx.x] - v;
}

__global__ __launch_bounds__(256) void scan3_kernel(int N, int EP) {
    int i = blockIdx.x * 256 + threadIdx.x;
    if (i < N) { g_start[i] += g_bsum[i >> 8]; g_cur[i] = 0; }
    if (i == 0) g_start[N] = EP;
}

__global__ __launch_bounds__(256) void scatter_kernel(const int* __restrict__ ei, int E, int EP) {
    int e = blockIdx.x * blockDim.x + threadIdx.x;
    if (e >= EP) return;
    int s, dn;
    if (e < E) { s = ei[e]; dn = ei[E + e]; } else { s = dn = e - E; }
    int pos = atomicAdd(&g_cur[dn], 1);
    g_csrc[g_start[dn] + pos] = s;
}

// ---------------- node kernels: 8 nodes/warp (R3-style GEMM) ----------------
__global__ __launch_bounds__(128) void node_e_kernel(const float* __restrict__ x,
                                                     const float* __restrict__ b_lin,
                                                     const float* __restrict__ att,
                                                     int N) {
    __shared__ float sx[4][8][D_];
    int w = threadIdx.x >> 5, l = threadIdx.x & 31;
    int base = blockIdx.x * 32 + w * 8;
    if (base >= N) return;
#pragma unroll
    for (int j = 0; j < 8; j++) {
        int n = min(base + j, N - 1);
        ((float4*)sx[w][j])[l] = ((const float4*)x)[n * 32 + l];
    }
    __syncwarp();
    unsigned long long acc[8][2];
#pragma unroll
    for (int j = 0; j < 8; j++) { acc[j][0] = 0ull; acc[j][1] = 0ull; }
    const ulonglong2* Wt = (const ulonglong2*)g_WtE;
#pragma unroll 2
    for (int k = 0; k < D_; k++) {
        ulonglong2 wv = Wt[k * 32 + l];
#pragma unroll
        for (int j = 0; j < 8; j++) {
            unsigned long long ss = pack2(sx[w][j][k]);
            ffma2(acc[j][0], ss, wv.x);
            ffma2(acc[j][1], ss, wv.y);
        }
    }
    float4 bv = ((const float4*)b_lin)[l];
    int h = l >> 3, j0 = (l & 7) * 4;
    const float* at  = att + h * 64 + j0;
    const float* at2 = at + 32;
#pragma unroll
    for (int j = 0; j < 8; j++) {
        int n = base + j;
        if (n >= N) break;
        float4 a = unpack4(acc[j][0], acc[j][1]);
        a.x += bv.x; a.y += bv.y; a.z += bv.z; a.w += bv.w;
        ((float4*)g_xe)[n * 32 + l] = a;
        float pi = a.x * at[0]  + a.y * at[1]  + a.z * at[2]  + a.w * at[3];
        float pj = a.x * at2[0] + a.y * at2[1] + a.z * at2[2] + a.w * at2[3];
#pragma unroll
        for (int o = 4; o; o >>= 1) {
            pi += __shfl_down_sync(0xffffffffu, pi, o, 8);
            pj += __shfl_down_sync(0xffffffffu, pj, o, 8);
        }
        if ((l & 7) == 0) { g_ai[n * 4 + h] = pi; g_aj[n * 4 + h] = pj; }
    }
}

__global__ __launch_bounds__(128) void node_h_kernel(const float* __restrict__ x,
                                                     const float* __restrict__ b_lin,
                                                     const float* __restrict__ att,
                                                     int N) {
    __shared__ float sx[4][8][D_];
    int w = threadIdx.x >> 5, l = threadIdx.x & 31;
    int base = blockIdx.x * 32 + w * 8;
    if (base >= N) return;
    // load + batched ||x||^2 reductions (8 interleaved trees)
    float pnx[8];
#pragma unroll
    for (int j = 0; j < 8; j++) {
        int n = min(base + j, N - 1);
        float4 xv = ((const float4*)x)[n * 32 + l];
        ((float4*)sx[w][j])[l] = xv;
        pnx[j] = d4(xv, xv);
    }
#pragma unroll
    for (int o = 16; o; o >>= 1) {
#pragma unroll
        for (int j = 0; j < 8; j++) pnx[j] += __shfl_xor_sync(0xffffffffu, pnx[j], o);
    }
    __syncwarp();
    unsigned long long acc[8][2];
#pragma unroll
    for (int j = 0; j < 8; j++) { acc[j][0] = 0ull; acc[j][1] = 0ull; }
    const ulonglong2* Wt = (const ulonglong2*)g_WtH;
#pragma unroll 2
    for (int k = 0; k < D_; k++) {
        ulonglong2 wv = Wt[k * 32 + l];
#pragma unroll
        for (int j = 0; j < 8; j++) {
            unsigned long long ss = pack2(sx[w][j][k]);
            ffma2(acc[j][0], ss, wv.x);
            ffma2(acc[j][1], ss, wv.y);
        }
    }
    // hoisted bias point hb = proj(expmap0(b_lin_h)); scalar norms
    float4 bvv = ((const float4*)b_lin)[l];
    float nb = fmaxf(sqrtf(wsum(d4(bvv, bvv))), MINNORM);
    float nhb = fminf(tanhf(nb), MAXN);
    float4 hb = f4s(bvv, nhb / nb);
    float y2 = nhb * nhb;

    // unpack mx, batched ||mx||^2 reductions
    float4 mx[8];
    float pm[8];
#pragma unroll
    for (int j = 0; j < 8; j++) {
        mx[j] = unpack4(acc[j][0], acc[j][1]);
        pm[j] = d4(mx[j], mx[j]);
    }
#pragma unroll
    for (int o = 16; o; o >>= 1) {
#pragma unroll
        for (int j = 0; j < 8; j++) pm[j] += __shfl_xor_sync(0xffffffffu, pm[j], o);
    }
    // scale factors (8 independent transcendental chains; compiler interleaves)
    float nmv[8];
#pragma unroll
    for (int j = 0; j < 8; j++) {
        float n_x = fmaxf(sqrtf(pnx[j]), MINNORM);
        float n_mx = fmaxf(sqrtf(pm[j]), MINNORM);
        nmv[j] = fminf(tanhf(n_mx / n_x * atanhc(n_x)), MAXN);
        float s = nmv[j] / n_mx;
        mx[j] = f4s(mx[j], s);           // mx now = mv
    }
    // batched <mv,hb> reductions
    float pxy[8];
#pragma unroll
    for (int j = 0; j < 8; j++) pxy[j] = d4(mx[j], hb);
#pragma unroll
    for (int o = 16; o; o >>= 1) {
#pragma unroll
        for (int j = 0; j < 8; j++) pxy[j] += __shfl_xor_sync(0xffffffffu, pxy[j], o);
    }

    int h = l >> 3, j0 = (l & 7) * 4;
    const float* at  = att + h * 64 + j0;
    const float* at2 = at + 32;
#pragma unroll
    for (int j = 0; j < 8; j++) {
        int n = base + j;
        if (n >= N) break;
        float x2 = nmv[j] * nmv[j];
        float xy = pxy[j];
        float A = 1.f + 2.f * xy + y2, B = 1.f - x2;
        float den = fmaxf(1.f + 2.f * xy + x2 * y2, MINNORM);
        float invden = 1.f / den;
        float nxh2 = fmaxf(A * A * x2 + 2.f * A * B * xy + B * B * y2, 0.f)
                     * invden * invden;
        float nxh = fmaxf(sqrtf(nxh2), MINNORM);
        float c = (nxh > MAXN) ? (MAXN / nxh) : 1.f;
        float4 xh = f4s(f4axby(A, mx[j], B, hb), invden * c);
        float nfin = c * nxh;
        float x2f = nfin * nfin;
        ((float4*)g_xh)[n * 32 + l] = xh;
        if (l == 0) g_x2[n] = x2f;
        float ncl = fmaxf(nfin, MINNORM);
        float4 lx = f4s(xh, atanhc(ncl) / ncl);
        ((float4*)g_lx)[n * 32 + l] = lx;
        float pi = lx.x * at[0]  + lx.y * at[1]  + lx.z * at[2]  + lx.w * at[3];
        float pj = lx.x * at2[0] + lx.y * at2[1] + lx.z * at2[2] + lx.w * at2[3];
#pragma unroll
        for (int o = 4; o; o >>= 1) {
            pi += __shfl_down_sync(0xffffffffu, pi, o, 8);
            pj += __shfl_down_sync(0xffffffffu, pj, o, 8);
        }
        if ((l & 7) == 0) { g_hi[n * 4 + h] = pi; g_hj[n * 4 + h] = pj; }
    }
}

// ---------------- fused edge (2 passes, unnormalized aggregation) + finalize ----------------
__global__ __launch_bounds__(256) void fused_edge_kernel(const float* __restrict__ b_e,
                                                         const float* __restrict__ b_h,
                                                         const float* __restrict__ att_hf,
                                                         const float* __restrict__ att_ef,
                                                         float* __restrict__ out, int N) {
    int w = (blockIdx.x * blockDim.x + threadIdx.x) >> 5;
    int l = threadIdx.x & 31;
    if (w >= N) return;
    int dn = w;
    int beg = g_start[dn], end = g_start[dn + 1];
    int h = l >> 3;
    bool leader = (l & 7) == 0;

    float4 xd  = ((const float4*)g_xh)[dn * 32 + l];
    float  x2d = g_x2[dn];
    float  ai_l = g_ai[dn * 4 + h];
    float  hi_l = g_hi[dn * 4 + h];

    // ---- Pass A: distances + euclid softmax-weighted aggregation (unnormalized) ----
    float sum_d = 0.f, sum_e = 0.f;
    float4 acc_e = make_float4(0.f, 0.f, 0.f, 0.f);
    int k = beg;
    for (; k + 4 <= end; k += 4) {
        int s0 = g_csrc[k + 0], s1 = g_csrc[k + 1];
        int s2 = g_csrc[k + 2], s3 = g_csrc[k + 3];
        float4 v0 = ((const float4*)g_xh)[s0 * 32 + l];
        float4 v1 = ((const float4*)g_xh)[s1 * 32 + l];
        float4 v2 = ((const float4*)g_xh)[s2 * 32 + l];
        float4 v3 = ((const float4*)g_xh)[s3 * 32 + l];
        float4 e0 = ((const float4*)g_xe)[s0 * 32 + l];
        float4 e1 = ((const float4*)g_xe)[s1 * 32 + l];
        float4 e2 = ((const float4*)g_xe)[s2 * 32 + l];
        float4 e3 = ((const float4*)g_xe)[s3 * 32 + l];
        float le0 = expf(lrelu(ai_l + g_aj[s0 * 4 + h]));
        float le1 = expf(lrelu(ai_l + g_aj[s1 * 4 + h]));
        float le2 = expf(lrelu(ai_l + g_aj[s2 * 4 + h]));
        float le3 = expf(lrelu(ai_l + g_aj[s3 * 4 + h]));
        acc_e.x = fmaf(le0, e0.x, fmaf(le1, e1.x, fmaf(le2, e2.x, fmaf(le3, e3.x, acc_e.x))));
        acc_e.y = fmaf(le0, e0.y, fmaf(le1, e1.y, fmaf(le2, e2.y, fmaf(le3, e3.y, acc_e.y))));
        acc_e.z = fmaf(le0, e0.z, fmaf(le1, e1.z, fmaf(le2, e2.z, fmaf(le3, e3.z, acc_e.z))));
        acc_e.w = fmaf(le0, e0.w, fmaf(le1, e1.w, fmaf(le2, e2.w, fmaf(le3, e3.w, acc_e.w))));
        if (leader) sum_e += le0 + le1 + le2 + le3;
        float p0 = d4(xd, v0), p1 = d4(xd, v1), p2 = d4(xd, v2), p3 = d4(xd, v3);
#pragma unroll
        for (int o = 16; o; o >>= 1) {
            p0 += __shfl_xor_sync(0xffffffffu, p0, o);
            p1 += __shfl_xor_sync(0xffffffffu, p1, o);
            p2 += __shfl_xor_sync(0xffffffffu, p2, o);
            p3 += __shfl_xor_sync(0xffffffffu, p3, o);
        }
        if (l < 4) {
            int ssel = (l == 0) ? s0 : (l == 1) ? s1 : (l == 2) ? s2 : s3;
            float pp = (l == 0) ? p0 : (l == 1) ? p1 : (l == 2) ? p2 : p3;
            float yy = g_x2[ssel];
            float A = 1.f - 2.f * pp + yy, B = 1.f - x2d;
            float den = fmaxf(1.f - 2.f * pp + x2d * yy, MINNORM);
            float num2 = fmaxf(A * A * x2d + B * B * yy - 2.f * A * B * pp, 0.f);
            float edd = expf(2.f * atanhc(sqrtf(num2) / den));
            g_de[k + l] = edd;
            sum_d += edd;
        }
    }
    for (; k < end; k++) {
        int s = g_csrc[k];
        float4 xs = ((const float4*)g_xh)[s * 32 + l];
        float4 es = ((const float4*)g_xe)[s * 32 + l];
        float le = expf(lrelu(ai_l + g_aj[s * 4 + h]));
        acc_e.x = fmaf(le, es.x, acc_e.x); acc_e.y = fmaf(le, es.y, acc_e.y);
        acc_e.z = fmaf(le, es.z, acc_e.z); acc_e.w = fmaf(le, es.w, acc_e.w);
        if (leader) sum_e += le;
        float xy = wsum(d4(xd, xs));
        float yy = g_x2[s];
        float A = 1.f - 2.f * xy + yy, B = 1.f - x2d;
        float den = fmaxf(1.f - 2.f * xy + x2d * yy, MINNORM);
        float num2 = fmaxf(A * A * x2d + B * B * yy - 2.f * A * B * xy, 0.f);
        float edd = expf(2.f * atanhc(sqrtf(num2) / den));
        if (l == 0) { g_de[k] = edd; sum_d += edd; }
    }
    float inv_sd = 1.f / (wsum(sum_d) + 1e-16f);

    // ---- Pass B: hyperbolic softmax-weighted aggregation (unnormalized) ----
    float sum_h = 0.f;
    float4 acc_h = make_float4(0.f, 0.f, 0.f, 0.f);
    k = beg;
    for (; k + 4 <= end; k += 4) {
        int s0 = g_csrc[k + 0], s1 = g_csrc[k + 1];
        int s2 = g_csrc[k + 2], s3 = g_csrc[k + 3];
        float4 l0 = ((const float4*)g_lx)[s0 * 32 + l];
        float4 l1 = ((const float4*)g_lx)[s1 * 32 + l];
        float4 l2 = ((const float4*)g_lx)[s2 * 32 + l];
        float4 l3 = ((const float4*)g_lx)[s3 * 32 + l];
        float d0 = g_de[k + 0] * inv_sd, d1 = g_de[k + 1] * inv_sd;
        float d2 = g_de[k + 2] * inv_sd, d3 = g_de[k + 3] * inv_sd;
        float a0 = expf(lrelu((hi_l + g_hj[s0 * 4 + h]) * d0));
        float a1 = expf(lrelu((hi_l + g_hj[s1 * 4 + h]) * d1));
        float a2 = expf(lrelu((hi_l + g_hj[s2 * 4 + h]) * d2));
        float a3 = expf(lrelu((hi_l + g_hj[s3 * 4 + h]) * d3));
        acc_h.x = fmaf(a0, l0.x, fmaf(a1, l1.x, fmaf(a2, l2.x, fmaf(a3, l3.x, acc_h.x))));
        acc_h.y = fmaf(a0, l0.y, fmaf(a1, l1.y, fmaf(a2, l2.y, fmaf(a3, l3.y, acc_h.y))));
        acc_h.z = fmaf(a0, l0.z, fmaf(a1, l1.z, fmaf(a2, l2.z, fmaf(a3, l3.z, acc_h.z))));
        acc_h.w = fmaf(a0, l0.w, fmaf(a1, l1.w, fmaf(a2, l2.w, fmaf(a3, l3.w, acc_h.w))));
        if (leader) sum_h += a0 + a1 + a2 + a3;
    }
    for (; k < end; k++) {
        int s = g_csrc[k];
        float4 ls = ((const float4*)g_lx)[s * 32 + l];
        float dsm = g_de[k] * inv_sd;
        float a = expf(lrelu((hi_l + g_hj[s * 4 + h]) * dsm));
        acc_h.x = fmaf(a, ls.x, acc_h.x); acc_h.y = fmaf(a, ls.y, acc_h.y);
        acc_h.z = fmaf(a, ls.z, acc_h.z); acc_h.w = fmaf(a, ls.w, acc_h.w);
        if (leader) sum_h += a;
    }

    float se = __shfl_sync(0xffffffffu, sum_e, h << 3);
    float sh = __shfl_sync(0xffffffffu, sum_h, h << 3);
    float inv_se = 1.f / (se + 1e-16f);
    float inv_sh = 1.f / (sh + 1e-16f);

    // ---- Finalize (scalar-norm algebra; 3 warp reductions) ----
    int n = dn;
    float4 be = ((const float4*)b_e)[l];
    float4 eo = make_float4(fmaxf(fmaf(acc_e.x, inv_se, be.x), 0.f),
                            fmaxf(fmaf(acc_e.y, inv_se, be.y), 0.f),
                            fmaxf(fmaf(acc_e.z, inv_se, be.z), 0.f),
                            fmaxf(fmaf(acc_e.w, inv_se, be.w), 0.f));
    float4 bh = ((const float4*)b_h)[l];
    float4 ot = make_float4(fmaxf(fmaf(acc_h.x, inv_sh, bh.x), 0.f),
                            fmaxf(fmaf(acc_h.y, inv_sh, bh.y), 0.f),
                            fmaxf(fmaf(acc_h.z, inv_sh, bh.z), 0.f),
                            fmaxf(fmaf(acc_h.w, inv_sh, bh.w), 0.f));
    float nt = fmaxf(sqrtf(wsum(d4(ot, ot))), MINNORM);
    float nho = fminf(tanhf(nt), MAXN);
    float4 ho = f4s(ot, nho / nt);
    float x2 = nho * nho;
    float ne2 = wsum(d4(eo, eo));
    float ne = fmaxf(sqrtf(ne2), MINNORM);
    float nye = fminf(tanhf(ne), MAXN);
    float4 ye = f4s(eo, nye / ne);
    float y2 = nye * nye;
    float xy = wsum(d4(ho, ye));
    float A = 1.f - 2.f * xy + y2, B = 1.f - x2;
    float den = fmaxf(1.f - 2.f * xy + x2 * y2, MINNORM);
    float num2 = fmaxf(A * A * x2 + B * B * y2 - 2.f * A * B * xy, 0.f);
    float r = 2.f * atanhc(sqrtf(num2) / den) * att_hf[0];
    float ny = fmaxf(nye, MINNORM);
    float t3 = tanhf(r * atanhc(ny));
    float kxe = t3 / ny;
    float nxe2 = fabsf(kxe) * nye;
    float c2 = (nxe2 > MAXN) ? (MAXN / fmaxf(nxe2, MINNORM)) : 1.f;
    float kxe2 = kxe * c2;
    float4 xe2 = f4s(ye, kxe2);
    float nxe2c = nxe2 * c2;
    float y2b = nxe2c * nxe2c;
    float xyb = xy * kxe2;
    float A2 = 1.f + 2.f * xyb + y2b, B2 = 1.f - x2;
    float den2 = fmaxf(1.f + 2.f * xyb + x2 * y2b, MINNORM);
    float invden2 = 1.f / den2;
    float nhf2 = fmaxf(A2 * A2 * x2 + 2.f * A2 * B2 * xyb + B2 * B2 * y2b, 0.f)
                 * invden2 * invden2;
    float nhf = fmaxf(sqrtf(nhf2), MINNORM);
    float c3 = (nhf > MAXN) ? (MAXN / nhf) : 1.f;
    float4 hf = f4s(f4axby(A2, ho, B2, xe2), invden2 * c3);
    float nclh = fmaxf(nho, MINNORM);
    float alh = atanhc(nclh);
    float kl = alh / nclh;
    float4 lh = f4s(ho, kl);
    float dot_ho_eo = xy * ne / nye;
    float de = (alh * alh - 2.f * kl * dot_ho_eo + ne2) * att_ef[0];
    float4 ef = make_float4(eo.x + de * lh.x, eo.y + de * lh.y,
                            eo.z + de * lh.z, eo.w + de * lh.w);
    ((float4*)out)[n * 32 + l] = hf;
    ((float4*)out)[(size_t)N * 32 + n * 32 + l] = ef;
}

// ---------------- launch: fork CSR chain onto side stream, join before fused ----------------
extern "C" void kernel_launch(void* const* d_in, const int* in_sizes, int n_in,
                              void* d_out, int out_size) {
    const float* x_e      = (const float*)d_in[0];
    const float* x_h      = (const float*)d_in[1];
    const int*   ei       = (const int*)d_in[2];
    const float* W_e      = (const float*)d_in[3];
    const float* b_lin_e  = (const float*)d_in[4];
    const float* att_e    = (const float*)d_in[5];
    const float* b_e      = (const float*)d_in[6];
    const float* W_h      = (const float*)d_in[7];
    const float* b_lin_h  = (const float*)d_in[8];
    const float* att_h    = (const float*)d_in[9];
    const float* b_h      = (const float*)d_in[10];
    const float* att_hf   = (const float*)d_in[11];
    const float* att_ef   = (const float*)d_in[12];
    float* out = (float*)d_out;

    int N  = in_sizes[0] / D_;
    int E  = in_sizes[2] / 2;
    int EP = E + N;
    int nsb = (N + 255) / 256;
    int ninit = (N > 2 * D_ * D_) ? N : 2 * D_ * D_;

    static cudaStream_t s2 = nullptr;
    static cudaEvent_t evFork = nullptr, evJoin = nullptr;
    if (s2 == nullptr) {
        cudaStreamCreateWithFlags(&s2, cudaStreamNonBlocking);
        cudaEventCreateWithFlags(&evFork, cudaEventDisableTiming);
        cudaEventCreateWithFlags(&evJoin, cudaEventDisableTiming);
    }

    // main stream: init (weights + deg zero), then node kernels
    init_kernel<<<(ninit + 255) / 256, 256>>>(W_e, W_h, N);
    cudaEventRecord(evFork, 0);

    // side stream: CSR build chain (depends only on init's deg zeroing)
    cudaStreamWaitEvent(s2, evFork, 0);
    count_kernel<<<(EP + 255) / 256, 256, 0, s2>>>(ei, E, EP);
    scan1_kernel<<<nsb, 256, 0, s2>>>(N);
    scan2_kernel<<<1, 256, 0, s2>>>(nsb);
    scan3_kernel<<<(N + 255) / 256, 256, 0, s2>>>(N, EP);
    scatter_kernel<<<(EP + 255) / 256, 256, 0, s2>>>(ei, E, EP);
    cudaEventRecord(evJoin, s2);

    // main stream: node feature kernels run concurrently with CSR chain
    node_e_kernel<<<(N + 31) / 32, 128>>>(x_e, b_lin_e, att_e, N);
    node_h_kernel<<<(N + 31) / 32, 128>>>(x_h, b_lin_h, att_h, N);

    // join, then fused edge + finalize
    cudaStreamWaitEvent(0, evJoin, 0);
    fused_edge_kernel<<<(N * 32 + 255) / 256, 256>>>(b_e, b_h, att_hf, att_ef, out, N);
}

// round 7
// speedup vs baseline: 2.8887x; 1.0374x over previous
#include <cuda_runtime.h>
#include <math.h>

#define D_ 128
#define NMAX 50016
#define EPMAX 550032
#define MAXN 0.99999f
#define MINNORM 1e-15f

// ---------------- scratch ----------------
__device__ float g_xe[NMAX * D_];
__device__ float g_xh[NMAX * D_];
__device__ float g_lx[NMAX * D_];
__device__ float g_ai[NMAX * 4];
__device__ float g_aj[NMAX * 4];
__device__ float g_hi[NMAX * 4];
__device__ float g_hj[NMAX * 4];
__device__ float g_x2[NMAX];
__device__ float g_de[EPMAX];       // exp(distance)
__device__ float g_WtE[D_ * D_];
__device__ float g_WtH[D_ * D_];
__device__ int   g_deg[NMAX];
__device__ int   g_cur[NMAX];
__device__ int   g_start[NMAX + 1];
__device__ int   g_csrc[EPMAX];
__device__ int   g_bsum[256];

// ---------------- helpers ----------------
__device__ __forceinline__ float atanhc(float x) {
    x = fminf(fmaxf(x, -1.0f + 1e-7f), 1.0f - 1e-7f);
    return atanhf(x);
}
__device__ __forceinline__ float wsum(float v) {
#pragma unroll
    for (int o = 16; o; o >>= 1) v += __shfl_xor_sync(0xffffffffu, v, o);
    return v;
}
__device__ __forceinline__ float d4(float4 a, float4 b) {
    return a.x * b.x + a.y * b.y + a.z * b.z + a.w * b.w;
}
__device__ __forceinline__ float4 f4s(float4 a, float s) {
    return make_float4(a.x * s, a.y * s, a.z * s, a.w * s);
}
__device__ __forceinline__ float4 f4axby(float a, float4 x, float b, float4 y) {
    return make_float4(a * x.x + b * y.x, a * x.y + b * y.y,
                       a * x.z + b * y.z, a * x.w + b * y.w);
}
__device__ __forceinline__ float lrelu(float v) { return v >= 0.f ? v : 0.2f * v; }

// packed f32x2 helpers (Blackwell FFMA2)
__device__ __forceinline__ void ffma2(unsigned long long &acc,
                                      unsigned long long a, unsigned long long b) {
    asm("fma.rn.f32x2 %0, %1, %2, %3;" : "=l"(acc) : "l"(a), "l"(b), "l"(acc));
}
__device__ __forceinline__ unsigned long long pack2(float s) {
    unsigned u = __float_as_uint(s);
    unsigned long long r;
    asm("mov.b64 %0, {%1, %1};" : "=l"(r) : "r"(u));
    return r;
}
__device__ __forceinline__ float4 unpack4(unsigned long long lo, unsigned long long hi) {
    float4 v;
    asm("mov.b64 {%0, %1}, %2;" : "=f"(v.x), "=f"(v.y) : "l"(lo));
    asm("mov.b64 {%0, %1}, %2;" : "=f"(v.z), "=f"(v.w) : "l"(hi));
    return v;
}

// ---------------- init: zero degrees + transpose weights ----------------
__global__ __launch_bounds__(256) void init_kernel(const float* __restrict__ We,
                                                   const float* __restrict__ Wh, int N) {
    int i = blockIdx.x * blockDim.x + threadIdx.x;
    if (i < N) g_deg[i] = 0;
    if (i < 2 * D_ * D_) {
        int m = i >> 14;
        int k = (i >> 7) & 127;
        int c = i & 127;
        if (m == 0) g_WtE[k * D_ + c] = We[c * D_ + k];
        else        g_WtH[k * D_ + c] = Wh[c * D_ + k];
    }
}

__global__ __launch_bounds__(256) void count_kernel(const int* __restrict__ ei, int E, int EP) {
    int e = blockIdx.x * blockDim.x + threadIdx.x;
    if (e >= EP) return;
    int dn = (e < E) ? ei[E + e] : (e - E);
    atomicAdd(&g_deg[dn], 1);
}

__global__ __launch_bounds__(256) void scan1_kernel(int N) {
    __shared__ int sm[256];
    int i = blockIdx.x * 256 + threadIdx.x;
    int v = (i < N) ? g_deg[i] : 0;
    sm[threadIdx.x] = v;
    __syncthreads();
#pragma unroll
    for (int d = 1; d < 256; d <<= 1) {
        int t = (threadIdx.x >= d) ? sm[threadIdx.x - d] : 0;
        __syncthreads();
        sm[threadIdx.x] += t;
        __syncthreads();
    }
    if (i < N) g_start[i] = sm[threadIdx.x] - v;
    if (threadIdx.x == 255) g_bsum[blockIdx.x] = sm[255];
}

__global__ __launch_bounds__(256) void scan2_kernel(int nb) {
    __shared__ int sm[256];
    int v = (threadIdx.x < nb) ? g_bsum[threadIdx.x] : 0;
    sm[threadIdx.x] = v;
    __syncthreads();
#pragma unroll
    for (int d = 1; d < 256; d <<= 1) {
        int t = (threadIdx.x >= d) ? sm[threadIdx.x - d] : 0;
        __syncthreads();
        sm[threadIdx.x] += t;
        __syncthreads();
    }
    g_bsum[threadIdx.x] = sm[threadIdx.x] - v;
}

__global__ __launch_bounds__(256) void scan3_kernel(int N, int EP) {
    int i = blockIdx.x * 256 + threadIdx.x;
    if (i < N) { g_start[i] += g_bsum[i >> 8]; g_cur[i] = 0; }
    if (i == 0) g_start[N] = EP;
}

__global__ __launch_bounds__(256) void scatter_kernel(const int* __restrict__ ei, int E, int EP) {
    int e = blockIdx.x * blockDim.x + threadIdx.x;
    if (e >= EP) return;
    int s, dn;
    if (e < E) { s = ei[e]; dn = ei[E + e]; } else { s = dn = e - E; }
    int pos = atomicAdd(&g_cur[dn], 1);
    g_csrc[g_start[dn] + pos] = s;
}

// ---------------- node kernels: 8 nodes/warp ----------------
__global__ __launch_bounds__(128) void node_e_kernel(const float* __restrict__ x,
                                                     const float* __restrict__ b_lin,
                                                     const float* __restrict__ att,
                                                     int N) {
    __shared__ float sx[4][8][D_];
    int w = threadIdx.x >> 5, l = threadIdx.x & 31;
    int base = blockIdx.x * 32 + w * 8;
    if (base >= N) return;
#pragma unroll
    for (int j = 0; j < 8; j++) {
        int n = min(base + j, N - 1);
        ((float4*)sx[w][j])[l] = ((const float4*)x)[n * 32 + l];
    }
    __syncwarp();
    unsigned long long acc[8][2];
#pragma unroll
    for (int j = 0; j < 8; j++) { acc[j][0] = 0ull; acc[j][1] = 0ull; }
    const ulonglong2* Wt = (const ulonglong2*)g_WtE;
#pragma unroll 2
    for (int k = 0; k < D_; k++) {
        ulonglong2 wv = Wt[k * 32 + l];
#pragma unroll
        for (int j = 0; j < 8; j++) {
            unsigned long long ss = pack2(sx[w][j][k]);
            ffma2(acc[j][0], ss, wv.x);
            ffma2(acc[j][1], ss, wv.y);
        }
    }
    float4 bv = ((const float4*)b_lin)[l];
    int h = l >> 3, j0 = (l & 7) * 4;
    const float* at  = att + h * 64 + j0;
    const float* at2 = at + 32;
#pragma unroll
    for (int j = 0; j < 8; j++) {
        int n = base + j;
        if (n >= N) break;
        float4 a = unpack4(acc[j][0], acc[j][1]);
        a.x += bv.x; a.y += bv.y; a.z += bv.z; a.w += bv.w;
        ((float4*)g_xe)[n * 32 + l] = a;
        float pi = a.x * at[0]  + a.y * at[1]  + a.z * at[2]  + a.w * at[3];
        float pj = a.x * at2[0] + a.y * at2[1] + a.z * at2[2] + a.w * at2[3];
#pragma unroll
        for (int o = 4; o; o >>= 1) {
            pi += __shfl_down_sync(0xffffffffu, pi, o, 8);
            pj += __shfl_down_sync(0xffffffffu, pj, o, 8);
        }
        if ((l & 7) == 0) { g_ai[n * 4 + h] = pi; g_aj[n * 4 + h] = pj; }
    }
}

__global__ __launch_bounds__(128) void node_h_kernel(const float* __restrict__ x,
                                                     const float* __restrict__ b_lin,
                                                     const float* __restrict__ att,
                                                     int N) {
    __shared__ float sx[4][8][D_];
    int w = threadIdx.x >> 5, l = threadIdx.x & 31;
    int base = blockIdx.x * 32 + w * 8;
    if (base >= N) return;
    float pnx[8];
#pragma unroll
    for (int j = 0; j < 8; j++) {
        int n = min(base + j, N - 1);
        float4 xv = ((const float4*)x)[n * 32 + l];
        ((float4*)sx[w][j])[l] = xv;
        pnx[j] = d4(xv, xv);
    }
#pragma unroll
    for (int o = 16; o; o >>= 1) {
#pragma unroll
        for (int j = 0; j < 8; j++) pnx[j] += __shfl_xor_sync(0xffffffffu, pnx[j], o);
    }
    __syncwarp();
    unsigned long long acc[8][2];
#pragma unroll
    for (int j = 0; j < 8; j++) { acc[j][0] = 0ull; acc[j][1] = 0ull; }
    const ulonglong2* Wt = (const ulonglong2*)g_WtH;
#pragma unroll 2
    for (int k = 0; k < D_; k++) {
        ulonglong2 wv = Wt[k * 32 + l];
#pragma unroll
        for (int j = 0; j < 8; j++) {
            unsigned long long ss = pack2(sx[w][j][k]);
            ffma2(acc[j][0], ss, wv.x);
            ffma2(acc[j][1], ss, wv.y);
        }
    }
    float4 bvv = ((const float4*)b_lin)[l];
    float nb = fmaxf(sqrtf(wsum(d4(bvv, bvv))), MINNORM);
    float nhb = fminf(tanhf(nb), MAXN);
    float4 hb = f4s(bvv, nhb / nb);
    float y2 = nhb * nhb;

    float4 mx[8];
    float pm[8];
#pragma unroll
    for (int j = 0; j < 8; j++) {
        mx[j] = unpack4(acc[j][0], acc[j][1]);
        pm[j] = d4(mx[j], mx[j]);
    }
#pragma unroll
    for (int o = 16; o; o >>= 1) {
#pragma unroll
        for (int j = 0; j < 8; j++) pm[j] += __shfl_xor_sync(0xffffffffu, pm[j], o);
    }
    float nmv[8];
#pragma unroll
    for (int j = 0; j < 8; j++) {
        float n_x = fmaxf(sqrtf(pnx[j]), MINNORM);
        float n_mx = fmaxf(sqrtf(pm[j]), MINNORM);
        nmv[j] = fminf(tanhf(n_mx / n_x * atanhc(n_x)), MAXN);
        float s = nmv[j] / n_mx;
        mx[j] = f4s(mx[j], s);
    }
    float pxy[8];
#pragma unroll
    for (int j = 0; j < 8; j++) pxy[j] = d4(mx[j], hb);
#pragma unroll
    for (int o = 16; o; o >>= 1) {
#pragma unroll
        for (int j = 0; j < 8; j++) pxy[j] += __shfl_xor_sync(0xffffffffu, pxy[j], o);
    }

    int h = l >> 3, j0 = (l & 7) * 4;
    const float* at  = att + h * 64 + j0;
    const float* at2 = at + 32;
#pragma unroll
    for (int j = 0; j < 8; j++) {
        int n = base + j;
        if (n >= N) break;
        float x2 = nmv[j] * nmv[j];
        float xy = pxy[j];
        float A = 1.f + 2.f * xy + y2, B = 1.f - x2;
        float den = fmaxf(1.f + 2.f * xy + x2 * y2, MINNORM);
        float invden = 1.f / den;
        float nxh2 = fmaxf(A * A * x2 + 2.f * A * B * xy + B * B * y2, 0.f)
                     * invden * invden;
        float nxh = fmaxf(sqrtf(nxh2), MINNORM);
        float c = (nxh > MAXN) ? (MAXN / nxh) : 1.f;
        float4 xh = f4s(f4axby(A, mx[j], B, hb), invden * c);
        float nfin = c * nxh;
        float x2f = nfin * nfin;
        ((float4*)g_xh)[n * 32 + l] = xh;
        if (l == 0) g_x2[n] = x2f;
        float ncl = fmaxf(nfin, MINNORM);
        float4 lx = f4s(xh, atanhc(ncl) / ncl);
        ((float4*)g_lx)[n * 32 + l] = lx;
        float pi = lx.x * at[0]  + lx.y * at[1]  + lx.z * at[2]  + lx.w * at[3];
        float pj = lx.x * at2[0] + lx.y * at2[1] + lx.z * at2[2] + lx.w * at2[3];
#pragma unroll
        for (int o = 4; o; o >>= 1) {
            pi += __shfl_down_sync(0xffffffffu, pi, o, 8);
            pj += __shfl_down_sync(0xffffffffu, pj, o, 8);
        }
        if ((l & 7) == 0) { g_hi[n * 4 + h] = pi; g_hj[n * 4 + h] = pj; }
    }
}

// ---------------- fused edge (fully masked 4-edge batches) + finalize ----------------
__global__ __launch_bounds__(256) void fused_edge_kernel(const float* __restrict__ b_e,
                                                         const float* __restrict__ b_h,
                                                         const float* __restrict__ att_hf,
                                                         const float* __restrict__ att_ef,
                                                         float* __restrict__ out, int N) {
    int w = (blockIdx.x * blockDim.x + threadIdx.x) >> 5;
    int l = threadIdx.x & 31;
    if (w >= N) return;
    int dn = w;
    int beg = g_start[dn], end = g_start[dn + 1];
    int h = l >> 3;
    bool leader = (l & 7) == 0;

    float4 xd  = ((const float4*)g_xh)[dn * 32 + l];
    float  x2d = g_x2[dn];
    float  ai_l = g_ai[dn * 4 + h];
    float  hi_l = g_hi[dn * 4 + h];

    // ---- Pass A: distances + euclid softmax-weighted aggregation (masked x4) ----
    float sum_d = 0.f, sum_e = 0.f;
    float4 acc_e = make_float4(0.f, 0.f, 0.f, 0.f);
    for (int k = beg; k < end; k += 4) {
        int k1 = min(k + 1, end - 1), k2 = min(k + 2, end - 1), k3 = min(k + 3, end - 1);
        float m1 = (k + 1 < end) ? 1.f : 0.f;
        float m2 = (k + 2 < end) ? 1.f : 0.f;
        float m3 = (k + 3 < end) ? 1.f : 0.f;
        int s0 = g_csrc[k], s1 = g_csrc[k1], s2 = g_csrc[k2], s3 = g_csrc[k3];
        float4 v0 = ((const float4*)g_xh)[s0 * 32 + l];
        float4 v1 = ((const float4*)g_xh)[s1 * 32 + l];
        float4 v2 = ((const float4*)g_xh)[s2 * 32 + l];
        float4 v3 = ((const float4*)g_xh)[s3 * 32 + l];
        float4 e0 = ((const float4*)g_xe)[s0 * 32 + l];
        float4 e1 = ((const float4*)g_xe)[s1 * 32 + l];
        float4 e2 = ((const float4*)g_xe)[s2 * 32 + l];
        float4 e3 = ((const float4*)g_xe)[s3 * 32 + l];
        float le0 = expf(lrelu(ai_l + g_aj[s0 * 4 + h]));
        float le1 = expf(lrelu(ai_l + g_aj[s1 * 4 + h])) * m1;
        float le2 = expf(lrelu(ai_l + g_aj[s2 * 4 + h])) * m2;
        float le3 = expf(lrelu(ai_l + g_aj[s3 * 4 + h])) * m3;
        acc_e.x = fmaf(le0, e0.x, fmaf(le1, e1.x, fmaf(le2, e2.x, fmaf(le3, e3.x, acc_e.x))));
        acc_e.y = fmaf(le0, e0.y, fmaf(le1, e1.y, fmaf(le2, e2.y, fmaf(le3, e3.y, acc_e.y))));
        acc_e.z = fmaf(le0, e0.z, fmaf(le1, e1.z, fmaf(le2, e2.z, fmaf(le3, e3.z, acc_e.z))));
        acc_e.w = fmaf(le0, e0.w, fmaf(le1, e1.w, fmaf(le2, e2.w, fmaf(le3, e3.w, acc_e.w))));
        if (leader) sum_e += le0 + le1 + le2 + le3;
        float p0 = d4(xd, v0), p1 = d4(xd, v1), p2 = d4(xd, v2), p3 = d4(xd, v3);
#pragma unroll
        for (int o = 16; o; o >>= 1) {
            p0 += __shfl_xor_sync(0xffffffffu, p0, o);
            p1 += __shfl_xor_sync(0xffffffffu, p1, o);
            p2 += __shfl_xor_sync(0xffffffffu, p2, o);
            p3 += __shfl_xor_sync(0xffffffffu, p3, o);
        }
        if (l < 4 && k + l < end) {
            int ssel = (l == 0) ? s0 : (l == 1) ? s1 : (l == 2) ? s2 : s3;
            float pp = (l == 0) ? p0 : (l == 1) ? p1 : (l == 2) ? p2 : p3;
            float yy = g_x2[ssel];
            float A = 1.f - 2.f * pp + yy, B = 1.f - x2d;
            float den = fmaxf(1.f - 2.f * pp + x2d * yy, MINNORM);
            float num2 = fmaxf(A * A * x2d + B * B * yy - 2.f * A * B * pp, 0.f);
            float edd = expf(2.f * atanhc(sqrtf(num2) / den));
            g_de[k + l] = edd;
            sum_d += edd;
        }
    }
    float inv_sd = 1.f / (wsum(sum_d) + 1e-16f);

    // ---- Pass B: hyperbolic softmax-weighted aggregation (masked x4) ----
    float sum_h = 0.f;
    float4 acc_h = make_float4(0.f, 0.f, 0.f, 0.f);
    for (int k = beg; k < end; k += 4) {
        int k1 = min(k + 1, end - 1), k2 = min(k + 2, end - 1), k3 = min(k + 3, end - 1);
        float m1 = (k + 1 < end) ? 1.f : 0.f;
        float m2 = (k + 2 < end) ? 1.f : 0.f;
        float m3 = (k + 3 < end) ? 1.f : 0.f;
        int s0 = g_csrc[k], s1 = g_csrc[k1], s2 = g_csrc[k2], s3 = g_csrc[k3];
        float4 l0 = ((const float4*)g_lx)[s0 * 32 + l];
        float4 l1 = ((const float4*)g_lx)[s1 * 32 + l];
        float4 l2 = ((const float4*)g_lx)[s2 * 32 + l];
        float4 l3 = ((const float4*)g_lx)[s3 * 32 + l];
        float d0 = g_de[k] * inv_sd,  d1 = g_de[k1] * inv_sd;
        float d2 = g_de[k2] * inv_sd, d3 = g_de[k3] * inv_sd;
        float a0 = expf(lrelu((hi_l + g_hj[s0 * 4 + h]) * d0));
        float a1 = expf(lrelu((hi_l + g_hj[s1 * 4 + h]) * d1)) * m1;
        float a2 = expf(lrelu((hi_l + g_hj[s2 * 4 + h]) * d2)) * m2;
        float a3 = expf(lrelu((hi_l + g_hj[s3 * 4 + h]) * d3)) * m3;
        acc_h.x = fmaf(a0, l0.x, fmaf(a1, l1.x, fmaf(a2, l2.x, fmaf(a3, l3.x, acc_h.x))));
        acc_h.y = fmaf(a0, l0.y, fmaf(a1, l1.y, fmaf(a2, l2.y, fmaf(a3, l3.y, acc_h.y))));
        acc_h.z = fmaf(a0, l0.z, fmaf(a1, l1.z, fmaf(a2, l2.z, fmaf(a3, l3.z, acc_h.z))));
        acc_h.w = fmaf(a0, l0.w, fmaf(a1, l1.w, fmaf(a2, l2.w, fmaf(a3, l3.w, acc_h.w))));
        if (leader) sum_h += a0 + a1 + a2 + a3;
    }

    float se = __shfl_sync(0xffffffffu, sum_e, h << 3);
    float sh = __shfl_sync(0xffffffffu, sum_h, h << 3);
    float inv_se = 1.f / (se + 1e-16f);
    float inv_sh = 1.f / (sh + 1e-16f);

    // ---- Finalize (scalar-norm algebra; 3 warp reductions) ----
    int n = dn;
    float4 be = ((const float4*)b_e)[l];
    float4 eo = make_float4(fmaxf(fmaf(acc_e.x, inv_se, be.x), 0.f),
                            fmaxf(fmaf(acc_e.y, inv_se, be.y), 0.f),
                            fmaxf(fmaf(acc_e.z, inv_se, be.z), 0.f),
                            fmaxf(fmaf(acc_e.w, inv_se, be.w), 0.f));
    float4 bh = ((const float4*)b_h)[l];
    float4 ot = make_float4(fmaxf(fmaf(acc_h.x, inv_sh, bh.x), 0.f),
                            fmaxf(fmaf(acc_h.y, inv_sh, bh.y), 0.f),
                            fmaxf(fmaf(acc_h.z, inv_sh, bh.z), 0.f),
                            fmaxf(fmaf(acc_h.w, inv_sh, bh.w), 0.f));
    float nt = fmaxf(sqrtf(wsum(d4(ot, ot))), MINNORM);
    float nho = fminf(tanhf(nt), MAXN);
    float4 ho = f4s(ot, nho / nt);
    float x2 = nho * nho;
    float ne2 = wsum(d4(eo, eo));
    float ne = fmaxf(sqrtf(ne2), MINNORM);
    float nye = fminf(tanhf(ne), MAXN);
    float4 ye = f4s(eo, nye / ne);
    float y2 = nye * nye;
    float xy = wsum(d4(ho, ye));
    float A = 1.f - 2.f * xy + y2, B = 1.f - x2;
    float den = fmaxf(1.f - 2.f * xy + x2 * y2, MINNORM);
    float num2 = fmaxf(A * A * x2 + B * B * y2 - 2.f * A * B * xy, 0.f);
    float r = 2.f * atanhc(sqrtf(num2) / den) * att_hf[0];
    float ny = fmaxf(nye, MINNORM);
    float t3 = tanhf(r * atanhc(ny));
    float kxe = t3 / ny;
    float nxe2 = fabsf(kxe) * nye;
    float c2 = (nxe2 > MAXN) ? (MAXN / fmaxf(nxe2, MINNORM)) : 1.f;
    float kxe2 = kxe * c2;
    float4 xe2 = f4s(ye, kxe2);
    float nxe2c = nxe2 * c2;
    float y2b = nxe2c * nxe2c;
    float xyb = xy * kxe2;
    float A2 = 1.f + 2.f * xyb + y2b, B2 = 1.f - x2;
    float den2 = fmaxf(1.f + 2.f * xyb + x2 * y2b, MINNORM);
    float invden2 = 1.f / den2;
    float nhf2 = fmaxf(A2 * A2 * x2 + 2.f * A2 * B2 * xyb + B2 * B2 * y2b, 0.f)
                 * invden2 * invden2;
    float nhf = fmaxf(sqrtf(nhf2), MINNORM);
    float c3 = (nhf > MAXN) ? (MAXN / nhf) : 1.f;
    float4 hf = f4s(f4axby(A2, ho, B2, xe2), invden2 * c3);
    float nclh = fmaxf(nho, MINNORM);
    float alh = atanhc(nclh);
    float kl = alh / nclh;
    float4 lh = f4s(ho, kl);
    float dot_ho_eo = xy * ne / nye;
    float de = (alh * alh - 2.f * kl * dot_ho_eo + ne2) * att_ef[0];
    float4 ef = make_float4(eo.x + de * lh.x, eo.y + de * lh.y,
                            eo.z + de * lh.z, eo.w + de * lh.w);
    ((float4*)out)[n * 32 + l] = hf;
    ((float4*)out)[(size_t)N * 32 + n * 32 + l] = ef;
}

// ---------------- launch: node_e / node_h / CSR on three concurrent streams ----------------
extern "C" void kernel_launch(void* const* d_in, const int* in_sizes, int n_in,
                              void* d_out, int out_size) {
    const float* x_e      = (const float*)d_in[0];
    const float* x_h      = (const float*)d_in[1];
    const int*   ei       = (const int*)d_in[2];
    const float* W_e      = (const float*)d_in[3];
    const float* b_lin_e  = (const float*)d_in[4];
    const float* att_e    = (const float*)d_in[5];
    const float* b_e      = (const float*)d_in[6];
    const float* W_h      = (const float*)d_in[7];
    const float* b_lin_h  = (const float*)d_in[8];
    const float* att_h    = (const float*)d_in[9];
    const float* b_h      = (const float*)d_in[10];
    const float* att_hf   = (const float*)d_in[11];
    const float* att_ef   = (const float*)d_in[12];
    float* out = (float*)d_out;

    int N  = in_sizes[0] / D_;
    int E  = in_sizes[2] / 2;
    int EP = E + N;
    int nsb = (N + 255) / 256;
    int ninit = (N > 2 * D_ * D_) ? N : 2 * D_ * D_;

    static cudaStream_t s2 = nullptr, s3 = nullptr;
    static cudaEvent_t evFork = nullptr, evJoin2 = nullptr, evJoin3 = nullptr;
    if (s2 == nullptr) {
        cudaStreamCreateWithFlags(&s2, cudaStreamNonBlocking);
        cudaStreamCreateWithFlags(&s3, cudaStreamNonBlocking);
        cudaEventCreateWithFlags(&evFork, cudaEventDisableTiming);
        cudaEventCreateWithFlags(&evJoin2, cudaEventDisableTiming);
        cudaEventCreateWithFlags(&evJoin3, cudaEventDisableTiming);
    }

    // main stream: init (weights + deg zero)
    init_kernel<<<(ninit + 255) / 256, 256>>>(W_e, W_h, N);
    cudaEventRecord(evFork, 0);

    // side stream s2: CSR build chain
    cudaStreamWaitEvent(s2, evFork, 0);
    count_kernel<<<(EP + 255) / 256, 256, 0, s2>>>(ei, E, EP);
    scan1_kernel<<<nsb, 256, 0, s2>>>(N);
    scan2_kernel<<<1, 256, 0, s2>>>(nsb);
    scan3_kernel<<<(N + 255) / 256, 256, 0, s2>>>(N, EP);
    scatter_kernel<<<(EP + 255) / 256, 256, 0, s2>>>(ei, E, EP);
    cudaEventRecord(evJoin2, s2);

    // side stream s3: hyperbolic node kernel (concurrent with node_e)
    cudaStreamWaitEvent(s3, evFork, 0);
    node_h_kernel<<<(N + 31) / 32, 128, 0, s3>>>(x_h, b_lin_h, att_h, N);
    cudaEventRecord(evJoin3, s3);

    // main stream: euclidean node kernel
    node_e_kernel<<<(N + 31) / 32, 128>>>(x_e, b_lin_e, att_e, N);

    // join all, then fused edge + finalize
    cudaStreamWaitEvent(0, evJoin2, 0);
    cudaStreamWaitEvent(0, evJoin3, 0);
    fused_edge_kernel<<<(N * 32 + 255) / 256, 256>>>(b_e, b_h, att_hf, att_ef, out, N);
}